// round 8
// baseline (speedup 1.0000x reference)
#include <cuda_runtime.h>
#include <cuda_bf16.h>
#include <math.h>
#include <stdint.h>

// ---------------- problem constants ----------------
#define B_    256
#define T_    100
#define INF   227
#define HID_  1024
#define NG    4096          // 4*HID
#define KP1   1280          // 227+1024 padded to 64
#define KP2   2048
#define SL    (B_*HID_)

#define W1SZ  (NG*KP1)
#define W2SZ  (NG*KP2)
#define WTOT  (W1SZ + 2*W2SZ)
#define A1SZ  (B_*KP1)
#define A2SZ  (B_*KP2)
#define APAR  (A1SZ + 2*A2SZ)

// SMEM tile geometry: 128 rows x 32 bf16, pitch 80B (conflict-free ldmatrix)
#define PITCH   80
#define TILEB   (128*PITCH)      // 10240 bytes per tile
#define STAGEB  (4*TILEB)        // Ah,Al,Bh,Bl = 40960
#define NSTAGE  2
#define DSMEM   (NSTAGE*STAGEB)  // 81920 bytes -> 2 CTAs/SM fit in 228KB

// ---------------- static device scratch ----------------
__device__ __align__(16) __nv_bfloat16 g_Wh[WTOT];     // weights hi, [n][k]
__device__ __align__(16) __nv_bfloat16 g_Wl[WTOT];     // weights lo
__device__ __align__(16) __nv_bfloat16 g_Ah[2*APAR];   // activations hi (ping-pong)
__device__ __align__(16) __nv_bfloat16 g_Al[2*APAR];   // activations lo
__device__ __align__(16) float g_bias[3*NG];           // bih+bhh, ifgo quads
__device__ __align__(16) float g_Bd[HID_*INF];         // Wd^T [k][o]
__device__ __align__(16) float g_c[3*SL];              // cell states fp32
__device__ __align__(16) float g_hist[(size_t)T_*SL];  // h2 history fp32

__device__ __forceinline__ float sigf_(float x) { return 1.0f / (1.0f + expf(-x)); }

// ---------------- PTX helpers (plain sm_80+ features only) ----------------
__device__ __forceinline__ uint32_t smem_u32(const void* p) {
    uint32_t a;
    asm("{ .reg .u64 t; cvta.to.shared.u64 t, %1; cvt.u32.u64 %0, t; }" : "=r"(a) : "l"(p));
    return a;
}
__device__ __forceinline__ void cp16(uint32_t d, const void* g) {
    asm volatile("cp.async.cg.shared.global [%0], [%1], 16;" :: "r"(d), "l"(g) : "memory");
}
__device__ __forceinline__ void cp_commit() {
    asm volatile("cp.async.commit_group;" ::: "memory");
}
__device__ __forceinline__ void ldm_x4(uint32_t* r, uint32_t a) {
    asm volatile("ldmatrix.sync.aligned.m8n8.x4.shared.b16 {%0,%1,%2,%3}, [%4];"
                 : "=r"(r[0]), "=r"(r[1]), "=r"(r[2]), "=r"(r[3]) : "r"(a));
}
__device__ __forceinline__ void mma16816(float* c, const uint32_t* a, uint32_t b0, uint32_t b1) {
    asm volatile("mma.sync.aligned.m16n8k16.row.col.f32.bf16.bf16.f32 "
                 "{%0,%1,%2,%3}, {%4,%5,%6,%7}, {%8,%9}, {%0,%1,%2,%3};"
                 : "+f"(c[0]), "+f"(c[1]), "+f"(c[2]), "+f"(c[3])
                 : "r"(a[0]), "r"(a[1]), "r"(a[2]), "r"(a[3]), "r"(b0), "r"(b1));
}

// ---------------- zero mutable state each replay ----------------
__global__ void k_zero() {
    const size_t CW = (size_t)3 * SL;
    const size_t AW = (size_t)APAR;
    const size_t N  = CW + 2 * AW;
    for (size_t i = (size_t)blockIdx.x * blockDim.x + threadIdx.x; i < N;
         i += (size_t)gridDim.x * blockDim.x) {
        if (i < CW)            g_c[i] = 0.0f;
        else if (i < CW + AW)  ((uint32_t*)g_Ah)[i - CW] = 0u;
        else                   ((uint32_t*)g_Al)[i - CW - AW] = 0u;
    }
}

// ---------------- weight reorder + bf16 split ----------------
__global__ void k_setup(const float* __restrict__ Wih1, const float* __restrict__ Whh1,
                        const float* __restrict__ Wih2, const float* __restrict__ Whh2,
                        const float* __restrict__ Wih3, const float* __restrict__ Whh3,
                        const float* __restrict__ bih1, const float* __restrict__ bhh1,
                        const float* __restrict__ bih2, const float* __restrict__ bhh2,
                        const float* __restrict__ bih3, const float* __restrict__ bhh3) {
    const long TOT = (long)WTOT + 3L * NG;
    for (long idx = (long)blockIdx.x * blockDim.x + threadIdx.x; idx < TOT;
         idx += (long)gridDim.x * blockDim.x) {
        long r = idx;
        if (r < (long)WTOT) {
            int z, n, k;
            if (r < W1SZ)              { z = 0; n = (int)(r / KP1); k = (int)(r % KP1); }
            else if (r < W1SZ + W2SZ)  { long q = r - W1SZ; z = 1; n = (int)(q / KP2); k = (int)(q % KP2); }
            else                       { long q = r - W1SZ - W2SZ; z = 2; n = (int)(q / KP2); k = (int)(q % KP2); }
            int R = (n & 3) * HID_ + (n >> 2);   // ifgo-quad reorder
            float w = 0.0f;
            if (z == 0) {
                if (k < INF)       w = Wih1[(size_t)R * INF + k];
                else if (k < 1251) w = Whh1[(size_t)R * HID_ + (k - INF)];
            } else if (z == 1) {
                w = (k < HID_) ? Wih2[(size_t)R * HID_ + k] : Whh2[(size_t)R * HID_ + (k - HID_)];
            } else {
                w = (k < HID_) ? Wih3[(size_t)R * HID_ + k] : Whh3[(size_t)R * HID_ + (k - HID_)];
            }
            __nv_bfloat16 hi = __float2bfloat16(w);
            __nv_bfloat16 lo = __float2bfloat16(w - __bfloat162float(hi));
            g_Wh[r] = hi; g_Wl[r] = lo;
            continue;
        }
        r -= WTOT;
        {
            int L = (int)(r / NG), n = (int)(r % NG);
            int R = (n & 3) * HID_ + (n >> 2);
            float v = (L == 0) ? bih1[R] + bhh1[R]
                    : (L == 1) ? bih2[R] + bhh2[R]
                               : bih3[R] + bhh3[R];
            g_bias[r] = v;
        }
    }
}

__global__ void k_setup_bd(const float* __restrict__ Wd) {
    int i = blockIdx.x * blockDim.x + threadIdx.x;
    if (i >= HID_ * INF) return;
    int k = i / INF, o = i % INF;
    g_Bd[i] = Wd[(size_t)o * HID_ + k];
}

// ---------------- teacher-forcing x split into layer1 A ----------------
__global__ void split_x(const float* __restrict__ rs, int t) {
    int i = blockIdx.x * blockDim.x + threadIdx.x;
    if (i >= B_ * INF) return;
    int b = i / INF, n = i % INF;
    float v = rs[(size_t)b * (T_ * INF) + (size_t)t * INF + n];
    __nv_bfloat16 hi = __float2bfloat16(v);
    __nv_bfloat16 lo = __float2bfloat16(v - __bfloat162float(hi));
    size_t o = (size_t)(t & 1) * APAR + (size_t)b * KP1 + n;
    g_Ah[o] = hi; g_Al[o] = lo;
}

// ---------------- fused HMMA gates GEMM + LSTM pointwise ----------------
// grid (32 ntiles, 2 mtiles, 3 layers), 256 thr = 8 warps (2 M x 4 N),
// CTA tile 128x128, warp tile 64x32, K-chunk 32, 2-stage cp.async,
// __launch_bounds__(256,2): TWO CTAs per SM so barrier/prologue bubbles of
// one CTA are filled by the other's MMA stream.
// Ootomo 3-term: acc += Ah*Bh + Ah*Bl + Al*Bh (fp32 accum).
__global__ void __launch_bounds__(256, 2) gates_kernel(int t) {
    extern __shared__ char dynsmem[];
    const int tid = threadIdx.x;
    const int warp = tid >> 5, lane = tid & 31;
    const int warpm = warp >> 2, warpn = warp & 3;
    const int z = blockIdx.z;
    const int p = t & 1, pn = p ^ 1;
    const int Kp  = (z == 0) ? KP1 : KP2;
    const int nch = Kp >> 5;                      // K-chunks of 32
    const size_t aoff = (z == 0) ? 0 : (z == 1) ? (size_t)A1SZ : (size_t)(A1SZ + A2SZ);
    const size_t woff = (z == 0) ? 0 : (z == 1) ? (size_t)W1SZ : (size_t)(W1SZ + W2SZ);
    const __nv_bfloat16* __restrict__ Ahg = g_Ah + (size_t)p * APAR + aoff;
    const __nv_bfloat16* __restrict__ Alg = g_Al + (size_t)p * APAR + aoff;
    const __nv_bfloat16* __restrict__ Whg = g_Wh + woff;
    const __nv_bfloat16* __restrict__ Wlg = g_Wl + woff;
    const int mbase = blockIdx.y * 128, nbase = blockIdx.x * 128;
    const uint32_t sbase = smem_u32(dynsmem);

    // ---- async stage loader: 2048 x 16B per stage, 8 per thread ----
    auto issue = [&](int ch) {
        const uint32_t sb = sbase + (ch & (NSTAGE - 1)) * STAGEB;
        const int k0 = ch << 5;
#pragma unroll
        for (int it = 0; it < 8; it++) {
            int s = it * 256 + tid;           // 0..2047
            int tile = s >> 9;                // 0:Ah 1:Al 2:Bh 3:Bl
            int r  = (s & 511) >> 2;
            int c4 = s & 3;
            uint32_t d = sb + tile * TILEB + r * PITCH + c4 * 16;
            const __nv_bfloat16* gp;
            if (tile == 0)      gp = Ahg + (size_t)(mbase + r) * Kp + k0 + c4 * 8;
            else if (tile == 1) gp = Alg + (size_t)(mbase + r) * Kp + k0 + c4 * 8;
            else if (tile == 2) gp = Whg + (size_t)(nbase + r) * Kp + k0 + c4 * 8;
            else                gp = Wlg + (size_t)(nbase + r) * Kp + k0 + c4 * 8;
            cp16(d, gp);
        }
        cp_commit();
    };

    float acc[4][4][4];
#pragma unroll
    for (int mf = 0; mf < 4; mf++)
#pragma unroll
        for (int nf = 0; nf < 4; nf++)
#pragma unroll
            for (int i = 0; i < 4; i++) acc[mf][nf][i] = 0.0f;

    issue(0);
    for (int ch = 0; ch < nch; ch++) {
        if (ch + 1 < nch) {
            issue(ch + 1);
            asm volatile("cp.async.wait_group 1;" ::: "memory");
        } else {
            asm volatile("cp.async.wait_group 0;" ::: "memory");
        }
        __syncthreads();
        const uint32_t sb = sbase + (ch & (NSTAGE - 1)) * STAGEB;
#pragma unroll
        for (int kk = 0; kk < 2; kk++) {
            uint32_t ah[4][4], al[4][4];
#pragma unroll
            for (int mf = 0; mf < 4; mf++) {
                uint32_t addr = sb + (uint32_t)(warpm * 64 + mf * 16 + (lane & 15)) * PITCH
                              + kk * 32 + (lane >> 4) * 16;
                ldm_x4(ah[mf], addr);
                ldm_x4(al[mf], addr + TILEB);
            }
            uint32_t bh[2][4], bl[2][4];
#pragma unroll
            for (int nf2 = 0; nf2 < 2; nf2++) {
                int nrow = warpn * 32 + nf2 * 16 + (lane & 7) + ((lane >> 4) << 3);
                uint32_t addr = sb + 2 * TILEB + (uint32_t)nrow * PITCH
                              + kk * 32 + ((lane >> 3) & 1) * 16;
                ldm_x4(bh[nf2], addr);
                ldm_x4(bl[nf2], addr + TILEB);
            }
#pragma unroll
            for (int mf = 0; mf < 4; mf++)
#pragma unroll
                for (int nf = 0; nf < 4; nf++) {
                    const int nf2 = nf >> 1, h = nf & 1;
                    uint32_t b0h = bh[nf2][h * 2], b1h = bh[nf2][h * 2 + 1];
                    uint32_t b0l = bl[nf2][h * 2], b1l = bl[nf2][h * 2 + 1];
                    mma16816(acc[mf][nf], ah[mf], b0h, b1h);
                    mma16816(acc[mf][nf], ah[mf], b0l, b1l);
                    mma16816(acc[mf][nf], al[mf], b0h, b1h);
                }
        }
        __syncthreads();
    }

    // ---- epilogue: shuffle c-frags into (i,f,g,o) quads, LSTM pointwise ----
    const int c     = lane & 3;
    const int pairq = c >> 1;
    const int pos   = c & 1;
    const int rbase = lane >> 2;

    float4 bias4[4];
#pragma unroll
    for (int nf = 0; nf < 4; nf++) {
        int n0 = nbase + warpn * 32 + nf * 8 + pairq * 4;
        bias4[nf] = *(const float4*)(g_bias + z * NG + n0);
    }

    float* cpz = g_c + (size_t)z * SL;
    size_t hb0, hb1 = 0; int st0;
    if (z == 0)      { hb0 = (size_t)pn * APAR + 227;                st0 = KP1;
                       hb1 = (size_t)pn * APAR + A1SZ; }
    else if (z == 1) { hb0 = (size_t)pn * APAR + A1SZ + 1024;        st0 = KP2;
                       hb1 = (size_t)pn * APAR + A1SZ + A2SZ; }
    else             { hb0 = (size_t)pn * APAR + A1SZ + A2SZ + 1024; st0 = KP2; }

#pragma unroll
    for (int mf = 0; mf < 4; mf++) {
#pragma unroll
        for (int nf = 0; nf < 4; nf++) {
            float a0 = acc[mf][nf][0], a1 = acc[mf][nf][1];
            float a2 = acc[mf][nf][2], a3 = acc[mf][nf][3];
            float p0 = __shfl_xor_sync(0xffffffffu, a0, 1);
            float p1 = __shfl_xor_sync(0xffffffffu, a1, 1);
            float p2 = __shfl_xor_sync(0xffffffffu, a2, 1);
            float p3 = __shfl_xor_sync(0xffffffffu, a3, 1);
            float iv, fv, gv, ov; int row;
            if (pos == 0) { iv = a0; fv = a1; gv = p0; ov = p1; row = rbase; }
            else          { iv = p2; fv = p3; gv = a2; ov = a3; row = rbase + 8; }
            iv += bias4[nf].x; fv += bias4[nf].y; gv += bias4[nf].z; ov += bias4[nf].w;

            int b  = mbase + warpm * 64 + mf * 16 + row;
            int n0 = nbase + warpn * 32 + nf * 8 + pairq * 4;
            int j  = n0 >> 2;
            size_t co = (size_t)b * HID_ + j;
            float cold = cpz[co];
            float cn = sigf_(fv) * cold + sigf_(iv) * tanhf(gv);
            float hn = sigf_(ov) * tanhf(cn);
            cpz[co] = cn;
            __nv_bfloat16 hi = __float2bfloat16(hn);
            __nv_bfloat16 lo = __float2bfloat16(hn - __bfloat162float(hi));
            size_t o0 = hb0 + (size_t)b * st0 + j;
            g_Ah[o0] = hi; g_Al[o0] = lo;
            if (z < 2) {
                size_t o1 = hb1 + (size_t)b * KP2 + j;
                g_Ah[o1] = hi; g_Al[o1] = lo;
            } else {
                g_hist[((size_t)t * B_ + b) * HID_ + j] = hn;
            }
        }
    }
}

// ---------------- feedback: x_{t+1} = h2[t] @ Wd^T + bd (free-run input) ----
__global__ __launch_bounds__(256) void feedback_kernel(int t, const float* __restrict__ bd) {
    __shared__ float sh[4][HID_];
    const int tid = threadIdx.x, bg = blockIdx.x;
    for (int i = tid; i < 4 * HID_; i += 256)
        sh[i >> 10][i & 1023] = g_hist[((size_t)t * B_ + bg * 4 + (i >> 10)) * HID_ + (i & 1023)];
    __syncthreads();
    const int n = tid;
    if (n >= INF) return;
    float acc[4] = {0, 0, 0, 0};
    for (int k = 0; k < HID_; k += 4) {
#pragma unroll
        for (int kk = 0; kk < 4; kk++) {
            float w = g_Bd[(size_t)(k + kk) * INF + n];
#pragma unroll
            for (int r = 0; r < 4; r++) acc[r] = fmaf(sh[r][k + kk], w, acc[r]);
        }
    }
    const int pnx = (t + 1) & 1;
#pragma unroll
    for (int r = 0; r < 4; r++) {
        float v = acc[r] + bd[n];
        __nv_bfloat16 hi = __float2bfloat16(v);
        __nv_bfloat16 lo = __float2bfloat16(v - __bfloat162float(hi));
        size_t o = (size_t)pnx * APAR + (size_t)(bg * 4 + r) * KP1 + n;
        g_Ah[o] = hi; g_Al[o] = lo;
    }
}

// ---------------- final batched dense: Out[t,b,:] = hist[t,b,:] @ Wd^T + bd ----
__global__ __launch_bounds__(256, 2)
void dense_kernel(float* __restrict__ out, const float* __restrict__ bd) {
    __shared__ __align__(16) float As[8][128];
    __shared__ __align__(16) float Bs[8][128];
    const int tid = threadIdx.x;
    const int m_base = blockIdx.y * 128;
    const int n_base = blockIdx.x * 128;
    const int am = tid >> 1, ak0 = (tid & 1) << 2;
    const int bkk = tid >> 5, bnn = (tid & 31) << 2;
    const int trow = (tid >> 4) << 3, tcol = (tid & 15) << 3;
    const int ridx = m_base + am;

    float acc[8][8];
#pragma unroll
    for (int r = 0; r < 8; r++)
#pragma unroll
        for (int cc = 0; cc < 8; cc++) acc[r][cc] = 0.0f;

    for (int k0 = 0; k0 < HID_; k0 += 8) {
#pragma unroll
        for (int i = 0; i < 4; i++)
            As[ak0 + i][am] = g_hist[(size_t)ridx * HID_ + k0 + ak0 + i];
#pragma unroll
        for (int i = 0; i < 4; i++) {
            int n = n_base + bnn + i;
            Bs[bkk][bnn + i] = (n < INF) ? g_Bd[(size_t)(k0 + bkk) * INF + n] : 0.0f;
        }
        __syncthreads();
#pragma unroll
        for (int kk = 0; kk < 8; kk++) {
            float a[8], bb[8];
            *reinterpret_cast<float4*>(a)      = *reinterpret_cast<const float4*>(&As[kk][trow]);
            *reinterpret_cast<float4*>(a + 4)  = *reinterpret_cast<const float4*>(&As[kk][trow + 4]);
            *reinterpret_cast<float4*>(bb)     = *reinterpret_cast<const float4*>(&Bs[kk][tcol]);
            *reinterpret_cast<float4*>(bb + 4) = *reinterpret_cast<const float4*>(&Bs[kk][tcol + 4]);
#pragma unroll
            for (int r = 0; r < 8; r++)
#pragma unroll
                for (int cc = 0; cc < 8; cc++)
                    acc[r][cc] = fmaf(a[r], bb[cc], acc[r][cc]);
        }
        __syncthreads();
    }
#pragma unroll
    for (int r = 0; r < 8; r++) {
        int row = m_base + trow + r;
        int tt = row >> 8, bb = row & 255;
#pragma unroll
        for (int cc = 0; cc < 8; cc++) {
            int n = n_base + tcol + cc;
            if (n < INF)
                out[(size_t)bb * (T_ * INF) + (size_t)tt * INF + n] = acc[r][cc] + bd[n];
        }
    }
}

// ---------------- launch ----------------
extern "C" void kernel_launch(void* const* d_in, const int* in_sizes, int n_in,
                              void* d_out, int out_size) {
    (void)in_sizes; (void)n_in; (void)out_size;
    const float* rs   = (const float*)d_in[0];
    const float* Wih1 = (const float*)d_in[1];
    const float* Whh1 = (const float*)d_in[2];
    const float* bih1 = (const float*)d_in[3];
    const float* bhh1 = (const float*)d_in[4];
    const float* Wih2 = (const float*)d_in[5];
    const float* Whh2 = (const float*)d_in[6];
    const float* bih2 = (const float*)d_in[7];
    const float* bhh2 = (const float*)d_in[8];
    const float* Wih3 = (const float*)d_in[9];
    const float* Whh3 = (const float*)d_in[10];
    const float* bih3 = (const float*)d_in[11];
    const float* bhh3 = (const float*)d_in[12];
    const float* Wd   = (const float*)d_in[13];
    const float* bd   = (const float*)d_in[14];
    float* out = (float*)d_out;

    cudaFuncSetAttribute(gates_kernel, cudaFuncAttributeMaxDynamicSharedMemorySize, DSMEM);

    k_zero<<<2048, 256>>>();
    k_setup<<<4096, 256>>>(Wih1, Whh1, Wih2, Whh2, Wih3, Whh3,
                           bih1, bhh1, bih2, bhh2, bih3, bhh3);
    k_setup_bd<<<(HID_ * INF + 255) / 256, 256>>>(Wd);

    for (int t = 0; t < T_; t++) {
        if ((t % 10) < 5)
            split_x<<<(B_ * INF + 255) / 256, 256>>>(rs, t);   // teacher forcing
        gates_kernel<<<dim3(32, 2, 3), 256, DSMEM>>>(t);
        if (t < T_ - 1 && ((t + 1) % 10) >= 5)
            feedback_kernel<<<64, 256>>>(t, bd);               // free-run input
    }
    dense_kernel<<<dim3(2, 200), 256>>>(out, bd);
}

// round 9
// speedup vs baseline: 1.0483x; 1.0483x over previous
#include <cuda_runtime.h>
#include <cuda_bf16.h>
#include <math.h>
#include <stdint.h>

// ---------------- problem constants ----------------
#define B_    256
#define T_    100
#define INF   227
#define HID_  1024
#define NG    4096          // 4*HID
#define KP1   1280          // 227+1024 padded to 64
#define KP2   2048
#define SL    (B_*HID_)

#define W1SZ  (NG*KP1)
#define W2SZ  (NG*KP2)
#define WTOT  (W1SZ + 2*W2SZ)
#define A1SZ  (B_*KP1)
#define A2SZ  (B_*KP2)
#define APAR  (A1SZ + 2*A2SZ)

// SMEM tile geometry: 128 rows x 32 bf16, pitch 80B (conflict-free ldmatrix)
#define PITCH   80
#define TILEB   (128*PITCH)      // 10240 bytes per tile
#define STAGEB  (4*TILEB)        // Ah,Al,Bh,Bl = 40960
#define NSTAGE  3
#define DSMEM   (NSTAGE*STAGEB)  // 122880 bytes

// ---------------- static device scratch ----------------
__device__ __align__(16) __nv_bfloat16 g_Wh[WTOT];     // weights hi, [n][k]
__device__ __align__(16) __nv_bfloat16 g_Wl[WTOT];     // weights lo
__device__ __align__(16) __nv_bfloat16 g_Ah[2*APAR];   // activations hi (ping-pong)
__device__ __align__(16) __nv_bfloat16 g_Al[2*APAR];   // activations lo
__device__ __align__(16) float g_bias[3*NG];           // bih+bhh, ifgo quads
__device__ __align__(16) float g_Bd[HID_*INF];         // Wd^T [k][o] (feedback)
__device__ __align__(16) __nv_bfloat16 g_BdH[256*HID_];// Wd bf16 hi, [n][k], rows>=227 zero
__device__ __align__(16) __nv_bfloat16 g_BdL[256*HID_];// Wd bf16 lo
__device__ __align__(16) float g_c[3*SL];              // cell states fp32
__device__ __align__(16) __nv_bfloat16 g_histH[(size_t)T_*SL]; // h2 history hi
__device__ __align__(16) __nv_bfloat16 g_histL[(size_t)T_*SL]; // h2 history lo

__device__ __forceinline__ float sigf_(float x) { return 1.0f / (1.0f + expf(-x)); }

// ---------------- PTX helpers (plain sm_80+ features only) ----------------
__device__ __forceinline__ uint32_t smem_u32(const void* p) {
    uint32_t a;
    asm("{ .reg .u64 t; cvta.to.shared.u64 t, %1; cvt.u32.u64 %0, t; }" : "=r"(a) : "l"(p));
    return a;
}
__device__ __forceinline__ void cp16(uint32_t d, const void* g) {
    asm volatile("cp.async.cg.shared.global [%0], [%1], 16;" :: "r"(d), "l"(g) : "memory");
}
__device__ __forceinline__ void cp_commit() {
    asm volatile("cp.async.commit_group;" ::: "memory");
}
__device__ __forceinline__ void ldm_x4(uint32_t* r, uint32_t a) {
    asm volatile("ldmatrix.sync.aligned.m8n8.x4.shared.b16 {%0,%1,%2,%3}, [%4];"
                 : "=r"(r[0]), "=r"(r[1]), "=r"(r[2]), "=r"(r[3]) : "r"(a));
}
__device__ __forceinline__ void mma16816(float* c, const uint32_t* a, uint32_t b0, uint32_t b1) {
    asm volatile("mma.sync.aligned.m16n8k16.row.col.f32.bf16.bf16.f32 "
                 "{%0,%1,%2,%3}, {%4,%5,%6,%7}, {%8,%9}, {%0,%1,%2,%3};"
                 : "+f"(c[0]), "+f"(c[1]), "+f"(c[2]), "+f"(c[3])
                 : "r"(a[0]), "r"(a[1]), "r"(a[2]), "r"(a[3]), "r"(b0), "r"(b1));
}

// ---------------- zero mutable state each replay ----------------
__global__ void k_zero() {
    const size_t CW = (size_t)3 * SL;
    const size_t AW = (size_t)APAR;
    const size_t N  = CW + 2 * AW;
    for (size_t i = (size_t)blockIdx.x * blockDim.x + threadIdx.x; i < N;
         i += (size_t)gridDim.x * blockDim.x) {
        if (i < CW)            g_c[i] = 0.0f;
        else if (i < CW + AW)  ((uint32_t*)g_Ah)[i - CW] = 0u;
        else                   ((uint32_t*)g_Al)[i - CW - AW] = 0u;
    }
}

// ---------------- weight reorder + bf16 split ----------------
__global__ void k_setup(const float* __restrict__ Wih1, const float* __restrict__ Whh1,
                        const float* __restrict__ Wih2, const float* __restrict__ Whh2,
                        const float* __restrict__ Wih3, const float* __restrict__ Whh3,
                        const float* __restrict__ bih1, const float* __restrict__ bhh1,
                        const float* __restrict__ bih2, const float* __restrict__ bhh2,
                        const float* __restrict__ bih3, const float* __restrict__ bhh3) {
    const long TOT = (long)WTOT + 3L * NG;
    for (long idx = (long)blockIdx.x * blockDim.x + threadIdx.x; idx < TOT;
         idx += (long)gridDim.x * blockDim.x) {
        long r = idx;
        if (r < (long)WTOT) {
            int z, n, k;
            if (r < W1SZ)              { z = 0; n = (int)(r / KP1); k = (int)(r % KP1); }
            else if (r < W1SZ + W2SZ)  { long q = r - W1SZ; z = 1; n = (int)(q / KP2); k = (int)(q % KP2); }
            else                       { long q = r - W1SZ - W2SZ; z = 2; n = (int)(q / KP2); k = (int)(q % KP2); }
            int R = (n & 3) * HID_ + (n >> 2);   // ifgo-quad reorder
            float w = 0.0f;
            if (z == 0) {
                if (k < INF)       w = Wih1[(size_t)R * INF + k];
                else if (k < 1251) w = Whh1[(size_t)R * HID_ + (k - INF)];
            } else if (z == 1) {
                w = (k < HID_) ? Wih2[(size_t)R * HID_ + k] : Whh2[(size_t)R * HID_ + (k - HID_)];
            } else {
                w = (k < HID_) ? Wih3[(size_t)R * HID_ + k] : Whh3[(size_t)R * HID_ + (k - HID_)];
            }
            __nv_bfloat16 hi = __float2bfloat16(w);
            __nv_bfloat16 lo = __float2bfloat16(w - __bfloat162float(hi));
            g_Wh[r] = hi; g_Wl[r] = lo;
            continue;
        }
        r -= WTOT;
        {
            int L = (int)(r / NG), n = (int)(r % NG);
            int R = (n & 3) * HID_ + (n >> 2);
            float v = (L == 0) ? bih1[R] + bhh1[R]
                    : (L == 1) ? bih2[R] + bhh2[R]
                               : bih3[R] + bhh3[R];
            g_bias[r] = v;
        }
    }
}

// Wd -> fp32 [k][o] (feedback) + bf16 hi/lo [n][k] padded to 256 rows (dense HMMA)
__global__ void k_setup_bd(const float* __restrict__ Wd) {
    int i = blockIdx.x * blockDim.x + threadIdx.x;
    if (i >= 256 * HID_) return;
    int n = i / HID_, k = i % HID_;
    float w = (n < INF) ? Wd[(size_t)n * HID_ + k] : 0.0f;
    __nv_bfloat16 hi = __float2bfloat16(w);
    __nv_bfloat16 lo = __float2bfloat16(w - __bfloat162float(hi));
    g_BdH[i] = hi; g_BdL[i] = lo;
    if (n < INF) g_Bd[(size_t)k * INF + n] = w;
}

// ---------------- teacher-forcing x split into layer1 A ----------------
__global__ void split_x(const float* __restrict__ rs, int t) {
    int i = blockIdx.x * blockDim.x + threadIdx.x;
    if (i >= B_ * INF) return;
    int b = i / INF, n = i % INF;
    float v = rs[(size_t)b * (T_ * INF) + (size_t)t * INF + n];
    __nv_bfloat16 hi = __float2bfloat16(v);
    __nv_bfloat16 lo = __float2bfloat16(v - __bfloat162float(hi));
    size_t o = (size_t)(t & 1) * APAR + (size_t)b * KP1 + n;
    g_Ah[o] = hi; g_Al[o] = lo;
}

// ---------------- fused HMMA gates GEMM + LSTM pointwise ----------------
// 1D grid of 192 jobs, LONG jobs (layers 2/3, 64 chunks) first, SHORT (layer 1,
// 40 chunks) last -> balanced 2nd wave. 256 thr = 8 warps (2M x 4N), CTA tile
// 128x128, warp tile 64x32, K-chunk 32, 3-stage cp.async ring, ONE barrier/chunk.
// Ootomo 3-term: acc += Ah*Bh + Ah*Bl + Al*Bh (fp32 accum).
__global__ void __launch_bounds__(256, 1) gates_kernel(int t) {
    extern __shared__ char dynsmem[];
    const int tid = threadIdx.x;
    const int warp = tid >> 5, lane = tid & 31;
    const int warpm = warp >> 2, warpn = warp & 3;

    // job decode: jid<128 -> z in {1,2}; jid>=128 -> z=0 (short, last)
    const int jid = blockIdx.x;
    int z, idx;
    if (jid < 128) { z = 1 + (jid & 1); idx = jid >> 1; }
    else           { z = 0;             idx = jid - 128; }
    const int nbase = (idx >> 1) * 128;
    const int mbase = (idx & 1) * 128;

    const int p = t & 1, pn = p ^ 1;
    const int Kp  = (z == 0) ? KP1 : KP2;
    const int nch = Kp >> 5;                      // K-chunks of 32
    const size_t aoff = (z == 0) ? 0 : (z == 1) ? (size_t)A1SZ : (size_t)(A1SZ + A2SZ);
    const size_t woff = (z == 0) ? 0 : (z == 1) ? (size_t)W1SZ : (size_t)(W1SZ + W2SZ);
    const __nv_bfloat16* __restrict__ Ahg = g_Ah + (size_t)p * APAR + aoff;
    const __nv_bfloat16* __restrict__ Alg = g_Al + (size_t)p * APAR + aoff;
    const __nv_bfloat16* __restrict__ Whg = g_Wh + woff;
    const __nv_bfloat16* __restrict__ Wlg = g_Wl + woff;
    const uint32_t sbase = smem_u32(dynsmem);

    // ---- async stage loader: 2048 x 16B per stage, 8 per thread ----
    auto issue = [&](int ch) {
        if (ch < nch) {
            const uint32_t sb = sbase + (ch % NSTAGE) * STAGEB;
            const int k0 = ch << 5;
#pragma unroll
            for (int it = 0; it < 8; it++) {
                int s = it * 256 + tid;           // 0..2047
                int tile = s >> 9;                // 0:Ah 1:Al 2:Bh 3:Bl
                int r  = (s & 511) >> 2;
                int c4 = s & 3;
                uint32_t d = sb + tile * TILEB + r * PITCH + c4 * 16;
                const __nv_bfloat16* gp;
                if (tile == 0)      gp = Ahg + (size_t)(mbase + r) * Kp + k0 + c4 * 8;
                else if (tile == 1) gp = Alg + (size_t)(mbase + r) * Kp + k0 + c4 * 8;
                else if (tile == 2) gp = Whg + (size_t)(nbase + r) * Kp + k0 + c4 * 8;
                else                gp = Wlg + (size_t)(nbase + r) * Kp + k0 + c4 * 8;
                cp16(d, gp);
            }
        }
        cp_commit();   // empty group at tail keeps pending-count invariant
    };

    float acc[4][4][4];
#pragma unroll
    for (int mf = 0; mf < 4; mf++)
#pragma unroll
        for (int nf = 0; nf < 4; nf++)
#pragma unroll
            for (int i = 0; i < 4; i++) acc[mf][nf][i] = 0.0f;

    issue(0); issue(1);
    for (int ch = 0; ch < nch; ch++) {
        asm volatile("cp.async.wait_group 1;" ::: "memory"); // group ch complete
        __syncthreads();   // stage ch visible to all; all warps done with ch-1
        issue(ch + 2);     // refill stage (ch+2)%3 (reads of it ended at ch-1)
        const uint32_t sb = sbase + (ch % NSTAGE) * STAGEB;
#pragma unroll
        for (int kk = 0; kk < 2; kk++) {
            uint32_t ah[4][4], al[4][4];
#pragma unroll
            for (int mf = 0; mf < 4; mf++) {
                uint32_t addr = sb + (uint32_t)(warpm * 64 + mf * 16 + (lane & 15)) * PITCH
                              + kk * 32 + (lane >> 4) * 16;
                ldm_x4(ah[mf], addr);
                ldm_x4(al[mf], addr + TILEB);
            }
            uint32_t bh[2][4], bl[2][4];
#pragma unroll
            for (int nf2 = 0; nf2 < 2; nf2++) {
                int nrow = warpn * 32 + nf2 * 16 + (lane & 7) + ((lane >> 4) << 3);
                uint32_t addr = sb + 2 * TILEB + (uint32_t)nrow * PITCH
                              + kk * 32 + ((lane >> 3) & 1) * 16;
                ldm_x4(bh[nf2], addr);
                ldm_x4(bl[nf2], addr + TILEB);
            }
#pragma unroll
            for (int mf = 0; mf < 4; mf++)
#pragma unroll
                for (int nf = 0; nf < 4; nf++) {
                    const int nf2 = nf >> 1, h = nf & 1;
                    uint32_t b0h = bh[nf2][h * 2], b1h = bh[nf2][h * 2 + 1];
                    uint32_t b0l = bl[nf2][h * 2], b1l = bl[nf2][h * 2 + 1];
                    mma16816(acc[mf][nf], ah[mf], b0h, b1h);
                    mma16816(acc[mf][nf], ah[mf], b0l, b1l);
                    mma16816(acc[mf][nf], al[mf], b0h, b1h);
                }
        }
    }

    // ---- epilogue: shuffle c-frags into (i,f,g,o) quads, LSTM pointwise ----
    const int c     = lane & 3;
    const int pairq = c >> 1;
    const int pos   = c & 1;
    const int rbase = lane >> 2;

    float4 bias4[4];
#pragma unroll
    for (int nf = 0; nf < 4; nf++) {
        int n0 = nbase + warpn * 32 + nf * 8 + pairq * 4;
        bias4[nf] = *(const float4*)(g_bias + z * NG + n0);
    }

    float* cpz = g_c + (size_t)z * SL;
    size_t hb0, hb1 = 0; int st0;
    if (z == 0)      { hb0 = (size_t)pn * APAR + 227;                st0 = KP1;
                       hb1 = (size_t)pn * APAR + A1SZ; }
    else if (z == 1) { hb0 = (size_t)pn * APAR + A1SZ + 1024;        st0 = KP2;
                       hb1 = (size_t)pn * APAR + A1SZ + A2SZ; }
    else             { hb0 = (size_t)pn * APAR + A1SZ + A2SZ + 1024; st0 = KP2; }

#pragma unroll
    for (int mf = 0; mf < 4; mf++) {
#pragma unroll
        for (int nf = 0; nf < 4; nf++) {
            float a0 = acc[mf][nf][0], a1 = acc[mf][nf][1];
            float a2 = acc[mf][nf][2], a3 = acc[mf][nf][3];
            float p0 = __shfl_xor_sync(0xffffffffu, a0, 1);
            float p1 = __shfl_xor_sync(0xffffffffu, a1, 1);
            float p2 = __shfl_xor_sync(0xffffffffu, a2, 1);
            float p3 = __shfl_xor_sync(0xffffffffu, a3, 1);
            float iv, fv, gv, ov; int row;
            if (pos == 0) { iv = a0; fv = a1; gv = p0; ov = p1; row = rbase; }
            else          { iv = p2; fv = p3; gv = a2; ov = a3; row = rbase + 8; }
            iv += bias4[nf].x; fv += bias4[nf].y; gv += bias4[nf].z; ov += bias4[nf].w;

            int b  = mbase + warpm * 64 + mf * 16 + row;
            int n0 = nbase + warpn * 32 + nf * 8 + pairq * 4;
            int j  = n0 >> 2;
            size_t co = (size_t)b * HID_ + j;
            float cold = cpz[co];
            float cn = sigf_(fv) * cold + sigf_(iv) * tanhf(gv);
            float hn = sigf_(ov) * tanhf(cn);
            cpz[co] = cn;
            __nv_bfloat16 hi = __float2bfloat16(hn);
            __nv_bfloat16 lo = __float2bfloat16(hn - __bfloat162float(hi));
            size_t o0 = hb0 + (size_t)b * st0 + j;
            g_Ah[o0] = hi; g_Al[o0] = lo;
            if (z < 2) {
                size_t o1 = hb1 + (size_t)b * KP2 + j;
                g_Ah[o1] = hi; g_Al[o1] = lo;
            } else {
                size_t ho = ((size_t)t * B_ + b) * HID_ + j;
                g_histH[ho] = hi; g_histL[ho] = lo;
            }
        }
    }
}

// ---------------- feedback: x_{t+1} = h2[t] @ Wd^T + bd (free-run input) ----
__global__ __launch_bounds__(256) void feedback_kernel(int t, const float* __restrict__ bd) {
    __shared__ float sh[4][HID_];
    const int tid = threadIdx.x, bg = blockIdx.x;
    for (int i = tid; i < 4 * HID_; i += 256) {
        size_t ho = ((size_t)t * B_ + bg * 4 + (i >> 10)) * HID_ + (i & 1023);
        sh[i >> 10][i & 1023] = __bfloat162float(g_histH[ho]) + __bfloat162float(g_histL[ho]);
    }
    __syncthreads();
    const int n = tid;
    if (n >= INF) return;
    float acc[4] = {0, 0, 0, 0};
    for (int k = 0; k < HID_; k += 4) {
#pragma unroll
        for (int kk = 0; kk < 4; kk++) {
            float w = g_Bd[(size_t)(k + kk) * INF + n];
#pragma unroll
            for (int r = 0; r < 4; r++) acc[r] = fmaf(sh[r][k + kk], w, acc[r]);
        }
    }
    const int pnx = (t + 1) & 1;
#pragma unroll
    for (int r = 0; r < 4; r++) {
        float v = acc[r] + bd[n];
        __nv_bfloat16 hi = __float2bfloat16(v);
        __nv_bfloat16 lo = __float2bfloat16(v - __bfloat162float(hi));
        size_t o = (size_t)pnx * APAR + (size_t)(bg * 4 + r) * KP1 + n;
        g_Ah[o] = hi; g_Al[o] = lo;
    }
}

// ---------------- final dense via HMMA: Out[t,b,:] = hist[t,b,:] @ Wd^T + bd ----
// Rows = t*256+b (25600), cols 227 (padded 256). Same engine as gates, K=1024.
__global__ void __launch_bounds__(256, 1) dense_kernel(float* __restrict__ out,
                                                       const float* __restrict__ bd) {
    extern __shared__ char dynsmem[];
    const int tid = threadIdx.x;
    const int warp = tid >> 5, lane = tid & 31;
    const int warpm = warp >> 2, warpn = warp & 3;
    const int mbase = (blockIdx.x >> 1) * 128;
    const int nbase = (blockIdx.x & 1) * 128;
    const int nch = HID_ >> 5;  // 32
    const uint32_t sbase = smem_u32(dynsmem);

    auto issue = [&](int ch) {
        if (ch < nch) {
            const uint32_t sb = sbase + (ch % NSTAGE) * STAGEB;
            const int k0 = ch << 5;
#pragma unroll
            for (int it = 0; it < 8; it++) {
                int s = it * 256 + tid;
                int tile = s >> 9;
                int r  = (s & 511) >> 2;
                int c4 = s & 3;
                uint32_t d = sb + tile * TILEB + r * PITCH + c4 * 16;
                const __nv_bfloat16* gp;
                if (tile == 0)      gp = g_histH + (size_t)(mbase + r) * HID_ + k0 + c4 * 8;
                else if (tile == 1) gp = g_histL + (size_t)(mbase + r) * HID_ + k0 + c4 * 8;
                else if (tile == 2) gp = g_BdH   + (size_t)(nbase + r) * HID_ + k0 + c4 * 8;
                else                gp = g_BdL   + (size_t)(nbase + r) * HID_ + k0 + c4 * 8;
                cp16(d, gp);
            }
        }
        cp_commit();
    };

    float acc[4][4][4];
#pragma unroll
    for (int mf = 0; mf < 4; mf++)
#pragma unroll
        for (int nf = 0; nf < 4; nf++)
#pragma unroll
            for (int i = 0; i < 4; i++) acc[mf][nf][i] = 0.0f;

    issue(0); issue(1);
    for (int ch = 0; ch < nch; ch++) {
        asm volatile("cp.async.wait_group 1;" ::: "memory");
        __syncthreads();
        issue(ch + 2);
        const uint32_t sb = sbase + (ch % NSTAGE) * STAGEB;
#pragma unroll
        for (int kk = 0; kk < 2; kk++) {
            uint32_t ah[4][4], al[4][4];
#pragma unroll
            for (int mf = 0; mf < 4; mf++) {
                uint32_t addr = sb + (uint32_t)(warpm * 64 + mf * 16 + (lane & 15)) * PITCH
                              + kk * 32 + (lane >> 4) * 16;
                ldm_x4(ah[mf], addr);
                ldm_x4(al[mf], addr + TILEB);
            }
            uint32_t bh[2][4], bl[2][4];
#pragma unroll
            for (int nf2 = 0; nf2 < 2; nf2++) {
                int nrow = warpn * 32 + nf2 * 16 + (lane & 7) + ((lane >> 4) << 3);
                uint32_t addr = sb + 2 * TILEB + (uint32_t)nrow * PITCH
                              + kk * 32 + ((lane >> 3) & 1) * 16;
                ldm_x4(bh[nf2], addr);
                ldm_x4(bl[nf2], addr + TILEB);
            }
#pragma unroll
            for (int mf = 0; mf < 4; mf++)
#pragma unroll
                for (int nf = 0; nf < 4; nf++) {
                    const int nf2 = nf >> 1, h = nf & 1;
                    uint32_t b0h = bh[nf2][h * 2], b1h = bh[nf2][h * 2 + 1];
                    uint32_t b0l = bl[nf2][h * 2], b1l = bl[nf2][h * 2 + 1];
                    mma16816(acc[mf][nf], ah[mf], b0h, b1h);
                    mma16816(acc[mf][nf], ah[mf], b0l, b1l);
                    mma16816(acc[mf][nf], al[mf], b0h, b1h);
                }
        }
    }

    // epilogue: native c-frag layout -> out[b][t*227+n]
    const int rbase = lane >> 2;
    const int cbase = (lane & 3) * 2;
#pragma unroll
    for (int mf = 0; mf < 4; mf++) {
#pragma unroll
        for (int nf = 0; nf < 4; nf++) {
#pragma unroll
            for (int i = 0; i < 4; i++) {
                int row = mbase + warpm * 64 + mf * 16 + rbase + (i >> 1) * 8;
                int n   = nbase + warpn * 32 + nf * 8 + cbase + (i & 1);
                if (n < INF) {
                    int tt = row >> 8, bb = row & 255;
                    out[(size_t)bb * (T_ * INF) + (size_t)tt * INF + n] =
                        acc[mf][nf][i] + bd[n];
                }
            }
        }
    }
}

// ---------------- launch ----------------
extern "C" void kernel_launch(void* const* d_in, const int* in_sizes, int n_in,
                              void* d_out, int out_size) {
    (void)in_sizes; (void)n_in; (void)out_size;
    const float* rs   = (const float*)d_in[0];
    const float* Wih1 = (const float*)d_in[1];
    const float* Whh1 = (const float*)d_in[2];
    const float* bih1 = (const float*)d_in[3];
    const float* bhh1 = (const float*)d_in[4];
    const float* Wih2 = (const float*)d_in[5];
    const float* Whh2 = (const float*)d_in[6];
    const float* bih2 = (const float*)d_in[7];
    const float* bhh2 = (const float*)d_in[8];
    const float* Wih3 = (const float*)d_in[9];
    const float* Whh3 = (const float*)d_in[10];
    const float* bih3 = (const float*)d_in[11];
    const float* bhh3 = (const float*)d_in[12];
    const float* Wd   = (const float*)d_in[13];
    const float* bd   = (const float*)d_in[14];
    float* out = (float*)d_out;

    cudaFuncSetAttribute(gates_kernel, cudaFuncAttributeMaxDynamicSharedMemorySize, DSMEM);
    cudaFuncSetAttribute(dense_kernel, cudaFuncAttributeMaxDynamicSharedMemorySize, DSMEM);

    k_zero<<<2048, 256>>>();
    k_setup<<<4096, 256>>>(Wih1, Whh1, Wih2, Whh2, Wih3, Whh3,
                           bih1, bhh1, bih2, bhh2, bih3, bhh3);
    k_setup_bd<<<(256 * HID_ + 255) / 256, 256>>>(Wd);

    for (int t = 0; t < T_; t++) {
        if ((t % 10) < 5)
            split_x<<<(B_ * INF + 255) / 256, 256>>>(rs, t);   // teacher forcing
        gates_kernel<<<192, 256, DSMEM>>>(t);
        if (t < T_ - 1 && ((t + 1) % 10) >= 5)
            feedback_kernel<<<64, 256>>>(t, bd);               // free-run input
    }
    dense_kernel<<<400, 256, DSMEM>>>(out, bd);
}

// round 10
// speedup vs baseline: 1.3532x; 1.2909x over previous
#include <cuda_runtime.h>
#include <cuda_fp16.h>
#include <math.h>
#include <stdint.h>

// ---------------- problem constants ----------------
#define B_    256
#define T_    100
#define INF   227
#define HID_  1024
#define NG    4096          // 4*HID
#define KP1   1280          // 227+1024 padded to 64
#define KP2   2048
#define SL    (B_*HID_)

#define W1SZ  (NG*KP1)
#define W2SZ  (NG*KP2)
#define WTOT  (W1SZ + 2*W2SZ)
#define A1SZ  (B_*KP1)
#define A2SZ  (B_*KP2)
#define APAR  (A1SZ + 2*A2SZ)

// SMEM tile geometry: 128 rows x 32 fp16, pitch 80B (conflict-free ldmatrix)
#define PITCH   80
#define TILEB   (128*PITCH)      // 10240 bytes per tile
#define NSTAGE  3
#define GSTAGEB (3*TILEB)        // gates: A, Bh, Bl = 30720
#define GSMEM   (NSTAGE*GSTAGEB) // 92160
#define DSTAGEB (4*TILEB)        // dense: Ah, Al, Bh, Bl = 40960
#define DSMEM_D (NSTAGE*DSTAGEB) // 122880

// ---------------- static device scratch ----------------
__device__ __align__(16) __half g_Wh[WTOT];     // weights hi (fp16), [n][k]
__device__ __align__(16) __half g_Wl[WTOT];     // weights lo (fp16)
__device__ __align__(16) __half g_A [2*APAR];   // activations fp16 (ping-pong)
__device__ __align__(16) float g_bias[3*NG];    // bih+bhh, ifgo quads
__device__ __align__(16) float g_Bd[HID_*INF];  // Wd^T [k][o] (feedback)
__device__ __align__(16) __half g_BdH[256*HID_];// Wd fp16 hi, [n][k], rows>=227 zero
__device__ __align__(16) __half g_BdL[256*HID_];// Wd fp16 lo
__device__ __align__(16) float g_c[3*SL];       // cell states fp32
__device__ __align__(16) __half g_histH[(size_t)T_*SL]; // h2 history hi
__device__ __align__(16) __half g_histL[(size_t)T_*SL]; // h2 history lo

__device__ __forceinline__ float sigf_(float x) { return 1.0f / (1.0f + expf(-x)); }

// ---------------- PTX helpers (plain sm_80+ features only) ----------------
__device__ __forceinline__ uint32_t smem_u32(const void* p) {
    uint32_t a;
    asm("{ .reg .u64 t; cvta.to.shared.u64 t, %1; cvt.u32.u64 %0, t; }" : "=r"(a) : "l"(p));
    return a;
}
__device__ __forceinline__ void cp16(uint32_t d, const void* g) {
    asm volatile("cp.async.cg.shared.global [%0], [%1], 16;" :: "r"(d), "l"(g) : "memory");
}
__device__ __forceinline__ void cp_commit() {
    asm volatile("cp.async.commit_group;" ::: "memory");
}
__device__ __forceinline__ void ldm_x4(uint32_t* r, uint32_t a) {
    asm volatile("ldmatrix.sync.aligned.m8n8.x4.shared.b16 {%0,%1,%2,%3}, [%4];"
                 : "=r"(r[0]), "=r"(r[1]), "=r"(r[2]), "=r"(r[3]) : "r"(a));
}
__device__ __forceinline__ void mma16816(float* c, const uint32_t* a, uint32_t b0, uint32_t b1) {
    asm volatile("mma.sync.aligned.m16n8k16.row.col.f32.f16.f16.f32 "
                 "{%0,%1,%2,%3}, {%4,%5,%6,%7}, {%8,%9}, {%0,%1,%2,%3};"
                 : "+f"(c[0]), "+f"(c[1]), "+f"(c[2]), "+f"(c[3])
                 : "r"(a[0]), "r"(a[1]), "r"(a[2]), "r"(a[3]), "r"(b0), "r"(b1));
}

// ---------------- zero mutable state each replay ----------------
__global__ void k_zero() {
    const size_t CW = (size_t)3 * SL;     // g_c floats
    const size_t AW = (size_t)APAR;       // g_A as uint32 words (2*APAR halfs)
    const size_t N  = CW + AW;
    for (size_t i = (size_t)blockIdx.x * blockDim.x + threadIdx.x; i < N;
         i += (size_t)gridDim.x * blockDim.x) {
        if (i < CW) g_c[i] = 0.0f;
        else        ((uint32_t*)g_A)[i - CW] = 0u;
    }
}

// ---------------- weight reorder + fp16 split ----------------
__global__ void k_setup(const float* __restrict__ Wih1, const float* __restrict__ Whh1,
                        const float* __restrict__ Wih2, const float* __restrict__ Whh2,
                        const float* __restrict__ Wih3, const float* __restrict__ Whh3,
                        const float* __restrict__ bih1, const float* __restrict__ bhh1,
                        const float* __restrict__ bih2, const float* __restrict__ bhh2,
                        const float* __restrict__ bih3, const float* __restrict__ bhh3) {
    const long TOT = (long)WTOT + 3L * NG;
    for (long idx = (long)blockIdx.x * blockDim.x + threadIdx.x; idx < TOT;
         idx += (long)gridDim.x * blockDim.x) {
        long r = idx;
        if (r < (long)WTOT) {
            int z, n, k;
            if (r < W1SZ)              { z = 0; n = (int)(r / KP1); k = (int)(r % KP1); }
            else if (r < W1SZ + W2SZ)  { long q = r - W1SZ; z = 1; n = (int)(q / KP2); k = (int)(q % KP2); }
            else                       { long q = r - W1SZ - W2SZ; z = 2; n = (int)(q / KP2); k = (int)(q % KP2); }
            int R = (n & 3) * HID_ + (n >> 2);   // ifgo-quad reorder
            float w = 0.0f;
            if (z == 0) {
                if (k < INF)       w = Wih1[(size_t)R * INF + k];
                else if (k < 1251) w = Whh1[(size_t)R * HID_ + (k - INF)];
            } else if (z == 1) {
                w = (k < HID_) ? Wih2[(size_t)R * HID_ + k] : Whh2[(size_t)R * HID_ + (k - HID_)];
            } else {
                w = (k < HID_) ? Wih3[(size_t)R * HID_ + k] : Whh3[(size_t)R * HID_ + (k - HID_)];
            }
            __half hi = __float2half_rn(w);
            __half lo = __float2half_rn(w - __half2float(hi));
            g_Wh[r] = hi; g_Wl[r] = lo;
            continue;
        }
        r -= WTOT;
        {
            int L = (int)(r / NG), n = (int)(r % NG);
            int R = (n & 3) * HID_ + (n >> 2);
            float v = (L == 0) ? bih1[R] + bhh1[R]
                    : (L == 1) ? bih2[R] + bhh2[R]
                               : bih3[R] + bhh3[R];
            g_bias[r] = v;
        }
    }
}

// Wd -> fp32 [k][o] (feedback) + fp16 hi/lo [n][k] padded to 256 rows (dense HMMA)
__global__ void k_setup_bd(const float* __restrict__ Wd) {
    int i = blockIdx.x * blockDim.x + threadIdx.x;
    if (i >= 256 * HID_) return;
    int n = i / HID_, k = i % HID_;
    float w = (n < INF) ? Wd[(size_t)n * HID_ + k] : 0.0f;
    __half hi = __float2half_rn(w);
    __half lo = __float2half_rn(w - __half2float(hi));
    g_BdH[i] = hi; g_BdL[i] = lo;
    if (n < INF) g_Bd[(size_t)k * INF + n] = w;
}

// ---------------- teacher-forcing x into layer1 A (fp16) ----------------
__global__ void split_x(const float* __restrict__ rs, int t) {
    int i = blockIdx.x * blockDim.x + threadIdx.x;
    if (i >= B_ * INF) return;
    int b = i / INF, n = i % INF;
    float v = rs[(size_t)b * (T_ * INF) + (size_t)t * INF + n];
    g_A[(size_t)(t & 1) * APAR + (size_t)b * KP1 + n] = __float2half_rn(v);
}

// ---------------- fused HMMA gates GEMM + LSTM pointwise ----------------
// 1D grid of 192 jobs (long layers first). 256 thr = 8 warps (2M x 4N),
// CTA tile 128x128, warp tile 64x32, K-chunk 32, 3-stage cp.async ring.
// 2-term fp16 split: acc += A*Bh + A*Bl  (weights exact to ~2^-22, activations fp16).
__global__ void __launch_bounds__(256, 1) gates_kernel(int t) {
    extern __shared__ char dynsmem[];
    const int tid = threadIdx.x;
    const int warp = tid >> 5, lane = tid & 31;
    const int warpm = warp >> 2, warpn = warp & 3;

    // job decode: jid<128 -> z in {1,2}; jid>=128 -> z=0 (short, last)
    const int jid = blockIdx.x;
    int z, idx;
    if (jid < 128) { z = 1 + (jid & 1); idx = jid >> 1; }
    else           { z = 0;             idx = jid - 128; }
    const int nbase = (idx >> 1) * 128;
    const int mbase = (idx & 1) * 128;

    const int p = t & 1, pn = p ^ 1;
    const int Kp  = (z == 0) ? KP1 : KP2;
    const int nch = Kp >> 5;                      // K-chunks of 32
    const size_t aoff = (z == 0) ? 0 : (z == 1) ? (size_t)A1SZ : (size_t)(A1SZ + A2SZ);
    const size_t woff = (z == 0) ? 0 : (z == 1) ? (size_t)W1SZ : (size_t)(W1SZ + W2SZ);
    const __half* __restrict__ Ag  = g_A  + (size_t)p * APAR + aoff;
    const __half* __restrict__ Whg = g_Wh + woff;
    const __half* __restrict__ Wlg = g_Wl + woff;
    const uint32_t sbase = smem_u32(dynsmem);

    // ---- async stage loader: 1536 x 16B per stage, 6 per thread ----
    auto issue = [&](int ch) {
        if (ch < nch) {
            const uint32_t sb = sbase + (ch % NSTAGE) * GSTAGEB;
            const int k0 = ch << 5;
#pragma unroll
            for (int it = 0; it < 6; it++) {
                int s = it * 256 + tid;           // 0..1535
                int tile = s >> 9;                // 0:A 1:Bh 2:Bl
                int r  = (s & 511) >> 2;
                int c4 = s & 3;
                uint32_t d = sb + tile * TILEB + r * PITCH + c4 * 16;
                const __half* gp;
                if (tile == 0)      gp = Ag  + (size_t)(mbase + r) * Kp + k0 + c4 * 8;
                else if (tile == 1) gp = Whg + (size_t)(nbase + r) * Kp + k0 + c4 * 8;
                else                gp = Wlg + (size_t)(nbase + r) * Kp + k0 + c4 * 8;
                cp16(d, gp);
            }
        }
        cp_commit();   // empty group at tail keeps pending-count invariant
    };

    float acc[4][4][4];
#pragma unroll
    for (int mf = 0; mf < 4; mf++)
#pragma unroll
        for (int nf = 0; nf < 4; nf++)
#pragma unroll
            for (int i = 0; i < 4; i++) acc[mf][nf][i] = 0.0f;

    issue(0); issue(1);
    for (int ch = 0; ch < nch; ch++) {
        asm volatile("cp.async.wait_group 1;" ::: "memory"); // group ch complete
        __syncthreads();   // stage ch visible; all warps done with ch-1
        issue(ch + 2);     // refill stage (ch+2)%3
        const uint32_t sb = sbase + (ch % NSTAGE) * GSTAGEB;
#pragma unroll
        for (int kk = 0; kk < 2; kk++) {
            uint32_t ah[4][4];
#pragma unroll
            for (int mf = 0; mf < 4; mf++) {
                uint32_t addr = sb + (uint32_t)(warpm * 64 + mf * 16 + (lane & 15)) * PITCH
                              + kk * 32 + (lane >> 4) * 16;
                ldm_x4(ah[mf], addr);
            }
            uint32_t bh[2][4], bl[2][4];
#pragma unroll
            for (int nf2 = 0; nf2 < 2; nf2++) {
                int nrow = warpn * 32 + nf2 * 16 + (lane & 7) + ((lane >> 4) << 3);
                uint32_t addr = sb + TILEB + (uint32_t)nrow * PITCH
                              + kk * 32 + ((lane >> 3) & 1) * 16;
                ldm_x4(bh[nf2], addr);
                ldm_x4(bl[nf2], addr + TILEB);
            }
#pragma unroll
            for (int mf = 0; mf < 4; mf++)
#pragma unroll
                for (int nf = 0; nf < 4; nf++) {
                    const int nf2 = nf >> 1, h = nf & 1;
                    mma16816(acc[mf][nf], ah[mf], bh[nf2][h * 2], bh[nf2][h * 2 + 1]);
                    mma16816(acc[mf][nf], ah[mf], bl[nf2][h * 2], bl[nf2][h * 2 + 1]);
                }
        }
    }

    // ---- epilogue: shuffle c-frags into (i,f,g,o) quads, LSTM pointwise ----
    const int c     = lane & 3;
    const int pairq = c >> 1;
    const int pos   = c & 1;
    const int rbase = lane >> 2;

    float4 bias4[4];
#pragma unroll
    for (int nf = 0; nf < 4; nf++) {
        int n0 = nbase + warpn * 32 + nf * 8 + pairq * 4;
        bias4[nf] = *(const float4*)(g_bias + z * NG + n0);
    }

    float* cpz = g_c + (size_t)z * SL;
    size_t hb0, hb1 = 0; int st0;
    if (z == 0)      { hb0 = (size_t)pn * APAR + 227;                st0 = KP1;
                       hb1 = (size_t)pn * APAR + A1SZ; }
    else if (z == 1) { hb0 = (size_t)pn * APAR + A1SZ + 1024;        st0 = KP2;
                       hb1 = (size_t)pn * APAR + A1SZ + A2SZ; }
    else             { hb0 = (size_t)pn * APAR + A1SZ + A2SZ + 1024; st0 = KP2; }

#pragma unroll
    for (int mf = 0; mf < 4; mf++) {
#pragma unroll
        for (int nf = 0; nf < 4; nf++) {
            float a0 = acc[mf][nf][0], a1 = acc[mf][nf][1];
            float a2 = acc[mf][nf][2], a3 = acc[mf][nf][3];
            float p0 = __shfl_xor_sync(0xffffffffu, a0, 1);
            float p1 = __shfl_xor_sync(0xffffffffu, a1, 1);
            float p2 = __shfl_xor_sync(0xffffffffu, a2, 1);
            float p3 = __shfl_xor_sync(0xffffffffu, a3, 1);
            float iv, fv, gv, ov; int row;
            if (pos == 0) { iv = a0; fv = a1; gv = p0; ov = p1; row = rbase; }
            else          { iv = p2; fv = p3; gv = a2; ov = a3; row = rbase + 8; }
            iv += bias4[nf].x; fv += bias4[nf].y; gv += bias4[nf].z; ov += bias4[nf].w;

            int b  = mbase + warpm * 64 + mf * 16 + row;
            int n0 = nbase + warpn * 32 + nf * 8 + pairq * 4;
            int j  = n0 >> 2;
            size_t co = (size_t)b * HID_ + j;
            float cold = cpz[co];
            float cn = sigf_(fv) * cold + sigf_(iv) * tanhf(gv);
            float hn = sigf_(ov) * tanhf(cn);
            cpz[co] = cn;
            __half hh = __float2half_rn(hn);
            g_A[hb0 + (size_t)b * st0 + j] = hh;
            if (z < 2) {
                g_A[hb1 + (size_t)b * KP2 + j] = hh;
            } else {
                size_t ho = ((size_t)t * B_ + b) * HID_ + j;
                g_histH[ho] = hh;
                g_histL[ho] = __float2half_rn(hn - __half2float(hh));
            }
        }
    }
}

// ---------------- feedback: x_{t+1} = h2[t] @ Wd^T + bd (free-run input) ----
__global__ __launch_bounds__(256) void feedback_kernel(int t, const float* __restrict__ bd) {
    __shared__ float sh[4][HID_];
    const int tid = threadIdx.x, bg = blockIdx.x;
    for (int i = tid; i < 4 * HID_; i += 256) {
        size_t ho = ((size_t)t * B_ + bg * 4 + (i >> 10)) * HID_ + (i & 1023);
        sh[i >> 10][i & 1023] = __half2float(g_histH[ho]) + __half2float(g_histL[ho]);
    }
    __syncthreads();
    const int n = tid;
    if (n >= INF) return;
    float acc[4] = {0, 0, 0, 0};
    for (int k = 0; k < HID_; k += 4) {
#pragma unroll
        for (int kk = 0; kk < 4; kk++) {
            float w = g_Bd[(size_t)(k + kk) * INF + n];
#pragma unroll
            for (int r = 0; r < 4; r++) acc[r] = fmaf(sh[r][k + kk], w, acc[r]);
        }
    }
    const int pnx = (t + 1) & 1;
#pragma unroll
    for (int r = 0; r < 4; r++) {
        float v = acc[r] + bd[n];
        g_A[(size_t)pnx * APAR + (size_t)(bg * 4 + r) * KP1 + n] = __float2half_rn(v);
    }
}

// ---------------- final dense via HMMA (3-term fp16, split hist + split Wd) ----
__global__ void __launch_bounds__(256, 1) dense_kernel(float* __restrict__ out,
                                                       const float* __restrict__ bd) {
    extern __shared__ char dynsmem[];
    const int tid = threadIdx.x;
    const int warp = tid >> 5, lane = tid & 31;
    const int warpm = warp >> 2, warpn = warp & 3;
    const int mbase = (blockIdx.x >> 1) * 128;
    const int nbase = (blockIdx.x & 1) * 128;
    const int nch = HID_ >> 5;  // 32
    const uint32_t sbase = smem_u32(dynsmem);

    auto issue = [&](int ch) {
        if (ch < nch) {
            const uint32_t sb = sbase + (ch % NSTAGE) * DSTAGEB;
            const int k0 = ch << 5;
#pragma unroll
            for (int it = 0; it < 8; it++) {
                int s = it * 256 + tid;
                int tile = s >> 9;
                int r  = (s & 511) >> 2;
                int c4 = s & 3;
                uint32_t d = sb + tile * TILEB + r * PITCH + c4 * 16;
                const __half* gp;
                if (tile == 0)      gp = g_histH + (size_t)(mbase + r) * HID_ + k0 + c4 * 8;
                else if (tile == 1) gp = g_histL + (size_t)(mbase + r) * HID_ + k0 + c4 * 8;
                else if (tile == 2) gp = g_BdH   + (size_t)(nbase + r) * HID_ + k0 + c4 * 8;
                else                gp = g_BdL   + (size_t)(nbase + r) * HID_ + k0 + c4 * 8;
                cp16(d, gp);
            }
        }
        cp_commit();
    };

    float acc[4][4][4];
#pragma unroll
    for (int mf = 0; mf < 4; mf++)
#pragma unroll
        for (int nf = 0; nf < 4; nf++)
#pragma unroll
            for (int i = 0; i < 4; i++) acc[mf][nf][i] = 0.0f;

    issue(0); issue(1);
    for (int ch = 0; ch < nch; ch++) {
        asm volatile("cp.async.wait_group 1;" ::: "memory");
        __syncthreads();
        issue(ch + 2);
        const uint32_t sb = sbase + (ch % NSTAGE) * DSTAGEB;
#pragma unroll
        for (int kk = 0; kk < 2; kk++) {
            uint32_t ah[4][4], al[4][4];
#pragma unroll
            for (int mf = 0; mf < 4; mf++) {
                uint32_t addr = sb + (uint32_t)(warpm * 64 + mf * 16 + (lane & 15)) * PITCH
                              + kk * 32 + (lane >> 4) * 16;
                ldm_x4(ah[mf], addr);
                ldm_x4(al[mf], addr + TILEB);
            }
            uint32_t bh[2][4], bl[2][4];
#pragma unroll
            for (int nf2 = 0; nf2 < 2; nf2++) {
                int nrow = warpn * 32 + nf2 * 16 + (lane & 7) + ((lane >> 4) << 3);
                uint32_t addr = sb + 2 * TILEB + (uint32_t)nrow * PITCH
                              + kk * 32 + ((lane >> 3) & 1) * 16;
                ldm_x4(bh[nf2], addr);
                ldm_x4(bl[nf2], addr + TILEB);
            }
#pragma unroll
            for (int mf = 0; mf < 4; mf++)
#pragma unroll
                for (int nf = 0; nf < 4; nf++) {
                    const int nf2 = nf >> 1, h = nf & 1;
                    uint32_t b0h = bh[nf2][h * 2], b1h = bh[nf2][h * 2 + 1];
                    uint32_t b0l = bl[nf2][h * 2], b1l = bl[nf2][h * 2 + 1];
                    mma16816(acc[mf][nf], ah[mf], b0h, b1h);
                    mma16816(acc[mf][nf], ah[mf], b0l, b1l);
                    mma16816(acc[mf][nf], al[mf], b0h, b1h);
                }
        }
    }

    // epilogue: native c-frag layout -> out[b][t*227+n]
    const int rbase = lane >> 2;
    const int cbase = (lane & 3) * 2;
#pragma unroll
    for (int mf = 0; mf < 4; mf++) {
#pragma unroll
        for (int nf = 0; nf < 4; nf++) {
#pragma unroll
            for (int i = 0; i < 4; i++) {
                int row = mbase + warpm * 64 + mf * 16 + rbase + (i >> 1) * 8;
                int n   = nbase + warpn * 32 + nf * 8 + cbase + (i & 1);
                if (n < INF) {
                    int tt = row >> 8, bb = row & 255;
                    out[(size_t)bb * (T_ * INF) + (size_t)tt * INF + n] =
                        acc[mf][nf][i] + bd[n];
                }
            }
        }
    }
}

// ---------------- launch ----------------
extern "C" void kernel_launch(void* const* d_in, const int* in_sizes, int n_in,
                              void* d_out, int out_size) {
    (void)in_sizes; (void)n_in; (void)out_size;
    const float* rs   = (const float*)d_in[0];
    const float* Wih1 = (const float*)d_in[1];
    const float* Whh1 = (const float*)d_in[2];
    const float* bih1 = (const float*)d_in[3];
    const float* bhh1 = (const float*)d_in[4];
    const float* Wih2 = (const float*)d_in[5];
    const float* Whh2 = (const float*)d_in[6];
    const float* bih2 = (const float*)d_in[7];
    const float* bhh2 = (const float*)d_in[8];
    const float* Wih3 = (const float*)d_in[9];
    const float* Whh3 = (const float*)d_in[10];
    const float* bih3 = (const float*)d_in[11];
    const float* bhh3 = (const float*)d_in[12];
    const float* Wd   = (const float*)d_in[13];
    const float* bd   = (const float*)d_in[14];
    float* out = (float*)d_out;

    cudaFuncSetAttribute(gates_kernel, cudaFuncAttributeMaxDynamicSharedMemorySize, GSMEM);
    cudaFuncSetAttribute(dense_kernel, cudaFuncAttributeMaxDynamicSharedMemorySize, DSMEM_D);

    k_zero<<<2048, 256>>>();
    k_setup<<<4096, 256>>>(Wih1, Whh1, Wih2, Whh2, Wih3, Whh3,
                           bih1, bhh1, bih2, bhh2, bih3, bhh3);
    k_setup_bd<<<(256 * HID_ + 255) / 256, 256>>>(Wd);

    for (int t = 0; t < T_; t++) {
        if ((t % 10) < 5)
            split_x<<<(B_ * INF + 255) / 256, 256>>>(rs, t);   // teacher forcing
        gates_kernel<<<192, 256, GSMEM>>>(t);
        if (t < T_ - 1 && ((t + 1) % 10) >= 5)
            feedback_kernel<<<64, 256>>>(t, bd);               // free-run input
    }
    dense_kernel<<<400, 256, DSMEM_D>>>(out, bd);
}

// round 11
// speedup vs baseline: 1.8717x; 1.3832x over previous
#include <cuda_runtime.h>
#include <cuda_fp16.h>
#include <math.h>
#include <stdint.h>

// ---------------- problem constants ----------------
#define B_    256
#define T_    100
#define INF   227
#define HID_  1024
#define NG    4096          // 4*HID
#define KP1   1280          // layer1 K: [h(1024) | x(227 pad 256)]
#define KP2   2048
#define SL    (B_*HID_)

#define W1SZ  (NG*KP1)
#define W2SZ  (NG*KP2)
#define WTOT  (W1SZ + 2*W2SZ)
#define A2SZ  (B_*KP2)      // one [h|h] activation panel
#define APAR  (2*A2SZ)      // layer2 + layer3 panels per parity

#define NJOBS 192

// SMEM tile geometry: 128 rows x 32 fp16, pitch 80B (conflict-free ldmatrix)
#define PITCH   80
#define TILEB   (128*PITCH)      // 10240 bytes per tile
#define NSTAGE  3
#define GSTAGEB (2*TILEB)        // gates: A, B = 20480
#define GSMEM   (NSTAGE*GSTAGEB) // 61440
#define DSTAGEB (4*TILEB)        // dense: Ah, Al, Bh, Bl = 40960
#define DSMEM_D (NSTAGE*DSTAGEB) // 122880

// ---------------- static device scratch ----------------
__device__ __align__(16) __half g_Wh[WTOT];     // weights fp16, [n][k]
__device__ __align__(16) __half g_A [2*APAR];   // [parity][layer2 panel | layer3 panel]
__device__ __align__(16) __half g_Ax[(size_t)T_*B_*256]; // per-step x frames (fp16, pad 256)
__device__ __align__(16) float g_bias[3*NG];    // bih+bhh, ifgo quads
__device__ __align__(16) float g_Bd[HID_*INF];  // Wd^T [k][o] (feedback)
__device__ __align__(16) __half g_BdH[256*HID_];// Wd fp16 hi, [n][k], rows>=227 zero
__device__ __align__(16) __half g_BdL[256*HID_];// Wd fp16 lo
__device__ __align__(16) float g_c[3*SL];       // cell states fp32
__device__ __align__(16) __half g_histH[(size_t)T_*SL]; // h2 history hi
__device__ __align__(16) __half g_histL[(size_t)T_*SL]; // h2 history lo
__device__ unsigned g_ticket[T_];               // per-step job tickets

__device__ __forceinline__ float sigf_(float x) { return 1.0f / (1.0f + expf(-x)); }

// ---------------- PTX helpers (plain sm_80+ features only) ----------------
__device__ __forceinline__ uint32_t smem_u32(const void* p) {
    uint32_t a;
    asm("{ .reg .u64 t; cvta.to.shared.u64 t, %1; cvt.u32.u64 %0, t; }" : "=r"(a) : "l"(p));
    return a;
}
__device__ __forceinline__ void cp16(uint32_t d, const void* g) {
    asm volatile("cp.async.cg.shared.global [%0], [%1], 16;" :: "r"(d), "l"(g) : "memory");
}
__device__ __forceinline__ void cp_commit() {
    asm volatile("cp.async.commit_group;" ::: "memory");
}
__device__ __forceinline__ void ldm_x4(uint32_t* r, uint32_t a) {
    asm volatile("ldmatrix.sync.aligned.m8n8.x4.shared.b16 {%0,%1,%2,%3}, [%4];"
                 : "=r"(r[0]), "=r"(r[1]), "=r"(r[2]), "=r"(r[3]) : "r"(a));
}
__device__ __forceinline__ void mma16816(float* c, const uint32_t* a, uint32_t b0, uint32_t b1) {
    asm volatile("mma.sync.aligned.m16n8k16.row.col.f32.f16.f16.f32 "
                 "{%0,%1,%2,%3}, {%4,%5,%6,%7}, {%8,%9}, {%0,%1,%2,%3};"
                 : "+f"(c[0]), "+f"(c[1]), "+f"(c[2]), "+f"(c[3])
                 : "r"(a[0]), "r"(a[1]), "r"(a[2]), "r"(a[3]), "r"(b0), "r"(b1));
}

// ---------------- zero mutable state each replay ----------------
__global__ void k_zero() {
    const size_t CW = (size_t)3 * SL;     // g_c floats
    const size_t AW = (size_t)APAR;       // g_A (2*APAR halfs = APAR words)
    const size_t N  = CW + AW + T_;
    for (size_t i = (size_t)blockIdx.x * blockDim.x + threadIdx.x; i < N;
         i += (size_t)gridDim.x * blockDim.x) {
        if (i < CW)           g_c[i] = 0.0f;
        else if (i < CW + AW) ((uint32_t*)g_A)[i - CW] = 0u;
        else                  g_ticket[i - CW - AW] = 0u;
    }
}

// ---------------- weight reorder + fp16 ----------------
// Layer1 K order: [h (k 0..1023) | x (k 1024..1250) | pad].
__global__ void k_setup(const float* __restrict__ Wih1, const float* __restrict__ Whh1,
                        const float* __restrict__ Wih2, const float* __restrict__ Whh2,
                        const float* __restrict__ Wih3, const float* __restrict__ Whh3,
                        const float* __restrict__ bih1, const float* __restrict__ bhh1,
                        const float* __restrict__ bih2, const float* __restrict__ bhh2,
                        const float* __restrict__ bih3, const float* __restrict__ bhh3) {
    const long TOT = (long)WTOT + 3L * NG;
    for (long idx = (long)blockIdx.x * blockDim.x + threadIdx.x; idx < TOT;
         idx += (long)gridDim.x * blockDim.x) {
        long r = idx;
        if (r < (long)WTOT) {
            int z, n, k;
            if (r < W1SZ)              { z = 0; n = (int)(r / KP1); k = (int)(r % KP1); }
            else if (r < W1SZ + W2SZ)  { long q = r - W1SZ; z = 1; n = (int)(q / KP2); k = (int)(q % KP2); }
            else                       { long q = r - W1SZ - W2SZ; z = 2; n = (int)(q / KP2); k = (int)(q % KP2); }
            int R = (n & 3) * HID_ + (n >> 2);   // ifgo-quad reorder
            float w = 0.0f;
            if (z == 0) {
                if (k < HID_)           w = Whh1[(size_t)R * HID_ + k];
                else if (k < HID_+INF)  w = Wih1[(size_t)R * INF + (k - HID_)];
            } else if (z == 1) {
                w = (k < HID_) ? Wih2[(size_t)R * HID_ + k] : Whh2[(size_t)R * HID_ + (k - HID_)];
            } else {
                w = (k < HID_) ? Wih3[(size_t)R * HID_ + k] : Whh3[(size_t)R * HID_ + (k - HID_)];
            }
            g_Wh[r] = __float2half_rn(w);
            continue;
        }
        r -= WTOT;
        {
            int L = (int)(r / NG), n = (int)(r % NG);
            int R = (n & 3) * HID_ + (n >> 2);
            float v = (L == 0) ? bih1[R] + bhh1[R]
                    : (L == 1) ? bih2[R] + bhh2[R]
                               : bih3[R] + bhh3[R];
            g_bias[r] = v;
        }
    }
}

// Wd -> fp32 [k][o] (feedback) + fp16 hi/lo [n][k] padded to 256 rows (dense HMMA)
__global__ void k_setup_bd(const float* __restrict__ Wd) {
    int i = blockIdx.x * blockDim.x + threadIdx.x;
    if (i >= 256 * HID_) return;
    int n = i / HID_, k = i % HID_;
    float w = (n < INF) ? Wd[(size_t)n * HID_ + k] : 0.0f;
    __half hi = __float2half_rn(w);
    __half lo = __float2half_rn(w - __half2float(hi));
    g_BdH[i] = hi; g_BdL[i] = lo;
    if (n < INF) g_Bd[(size_t)k * INF + n] = w;
}

// ---------------- stage ALL x frames upfront (teacher frames + zero pads) ----
__global__ void stage_x(const float* __restrict__ rs) {
    long i = (long)blockIdx.x * blockDim.x + threadIdx.x;
    if (i >= (long)T_ * B_ * 256) return;
    int n = (int)(i & 255);
    int b = (int)((i >> 8) & 255);
    int t = (int)(i >> 16);
    float v = 0.0f;
    if (n < INF && (t % 10) < 5)
        v = rs[(size_t)b * (T_ * INF) + (size_t)t * INF + n];
    g_Ax[i] = __float2half_rn(v);
}

// ---------------- persistent fused HMMA gates GEMM + LSTM pointwise ----------
// 152 persistent CTAs pop jobs from an atomic ticket queue (long jobs first ->
// LPT schedule, makespan 104 chunk-units vs 128 naive). 256 thr = 8 warps
// (2M x 4N), CTA tile 128x128, warp tile 64x32, K-chunk 32, 3-stage cp.async.
// Pure fp16 1-term: acc += A*W (fp32 accumulate).
__global__ void __launch_bounds__(256, 1) gates_kernel(int t) {
    extern __shared__ char dynsmem[];
    __shared__ int s_job;
    const int tid = threadIdx.x;
    const int warp = tid >> 5, lane = tid & 31;
    const int warpm = warp >> 2, warpn = warp & 3;
    const int p = t & 1, pn = p ^ 1;
    const uint32_t sbase = smem_u32(dynsmem);
    const __half* __restrict__ Apar = g_A + (size_t)p * APAR;

    for (;;) {
        if (tid == 0) s_job = (int)atomicAdd(&g_ticket[t], 1u);
        __syncthreads();
        const int jid = s_job;
        if (jid >= NJOBS) return;

        // job decode: jid<128 -> z in {1,2} (64 chunks); jid>=128 -> z=0 (40 chunks)
        int z, idx;
        if (jid < 128) { z = 1 + (jid & 1); idx = jid >> 1; }
        else           { z = 0;             idx = jid - 128; }
        const int nbase = (idx >> 1) * 128;
        const int mbase = (idx & 1) * 128;
        const int Kp  = (z == 0) ? KP1 : KP2;
        const int nch = Kp >> 5;
        const size_t woff = (z == 0) ? 0 : (z == 1) ? (size_t)W1SZ : (size_t)(W1SZ + W2SZ);
        const __half* __restrict__ Wg = g_Wh + woff;
        // A h-panel: z0/z1 -> layer2 panel (h0 cols 0..1023 [+h1]); z2 -> layer3 panel
        const __half* __restrict__ Ah = Apar + ((z == 2) ? (size_t)A2SZ : 0);
        const __half* __restrict__ Ax = g_Ax + (size_t)t * (B_ * 256);

        // ---- async stage loader: 1024 x 16B per stage, 4 per thread ----
        auto issue = [&](int ch) {
            if (ch < nch) {
                const uint32_t sb = sbase + (ch % NSTAGE) * GSTAGEB;
                const int k0 = ch << 5;
#pragma unroll
                for (int it = 0; it < 4; it++) {
                    int s = it * 256 + tid;           // 0..1023
                    int tile = s >> 9;                // 0:A 1:B
                    int r  = (s & 511) >> 2;
                    int c4 = s & 3;
                    uint32_t d = sb + tile * TILEB + r * PITCH + c4 * 16;
                    const __half* gp;
                    if (tile == 0) {
                        if (z == 0 && ch >= 32)
                            gp = Ax + (size_t)(mbase + r) * 256 + (k0 - 1024) + c4 * 8;
                        else
                            gp = Ah + (size_t)(mbase + r) * KP2 + k0 + c4 * 8;
                    } else {
                        gp = Wg + (size_t)(nbase + r) * Kp + k0 + c4 * 8;
                    }
                    cp16(d, gp);
                }
            }
            cp_commit();
        };

        float acc[4][4][4];
#pragma unroll
        for (int mf = 0; mf < 4; mf++)
#pragma unroll
            for (int nf = 0; nf < 4; nf++)
#pragma unroll
                for (int i = 0; i < 4; i++) acc[mf][nf][i] = 0.0f;

        issue(0); issue(1);
        for (int ch = 0; ch < nch; ch++) {
            asm volatile("cp.async.wait_group 1;" ::: "memory");
            __syncthreads();
            issue(ch + 2);
            const uint32_t sb = sbase + (ch % NSTAGE) * GSTAGEB;
#pragma unroll
            for (int kk = 0; kk < 2; kk++) {
                uint32_t ah[4][4];
#pragma unroll
                for (int mf = 0; mf < 4; mf++) {
                    uint32_t addr = sb + (uint32_t)(warpm * 64 + mf * 16 + (lane & 15)) * PITCH
                                  + kk * 32 + (lane >> 4) * 16;
                    ldm_x4(ah[mf], addr);
                }
                uint32_t bh[2][4];
#pragma unroll
                for (int nf2 = 0; nf2 < 2; nf2++) {
                    int nrow = warpn * 32 + nf2 * 16 + (lane & 7) + ((lane >> 4) << 3);
                    uint32_t addr = sb + TILEB + (uint32_t)nrow * PITCH
                                  + kk * 32 + ((lane >> 3) & 1) * 16;
                    ldm_x4(bh[nf2], addr);
                }
#pragma unroll
                for (int mf = 0; mf < 4; mf++)
#pragma unroll
                    for (int nf = 0; nf < 4; nf++) {
                        const int nf2 = nf >> 1, h = nf & 1;
                        mma16816(acc[mf][nf], ah[mf], bh[nf2][h * 2], bh[nf2][h * 2 + 1]);
                    }
            }
        }

        // ---- epilogue: shuffle c-frags into (i,f,g,o) quads, LSTM pointwise ----
        const int c     = lane & 3;
        const int pairq = c >> 1;
        const int pos   = c & 1;
        const int rbase = lane >> 2;

        float* cpz = g_c + (size_t)z * SL;
        __half* dst0; __half* dst1 = nullptr;
        if (z == 0)      { dst0 = g_A + (size_t)pn * APAR; }                       // h0 -> L2 panel lo
        else if (z == 1) { dst0 = g_A + (size_t)pn * APAR + 1024;                  // h1 -> L2 panel hi
                           dst1 = g_A + (size_t)pn * APAR + A2SZ; }                // h1 -> L3 panel lo
        else             { dst0 = g_A + (size_t)pn * APAR + A2SZ + 1024; }         // h2 -> L3 panel hi

#pragma unroll
        for (int mf = 0; mf < 4; mf++) {
#pragma unroll
            for (int nf = 0; nf < 4; nf++) {
                float a0 = acc[mf][nf][0], a1 = acc[mf][nf][1];
                float a2 = acc[mf][nf][2], a3 = acc[mf][nf][3];
                float p0 = __shfl_xor_sync(0xffffffffu, a0, 1);
                float p1 = __shfl_xor_sync(0xffffffffu, a1, 1);
                float p2 = __shfl_xor_sync(0xffffffffu, a2, 1);
                float p3 = __shfl_xor_sync(0xffffffffu, a3, 1);
                float iv, fv, gv, ov; int row;
                if (pos == 0) { iv = a0; fv = a1; gv = p0; ov = p1; row = rbase; }
                else          { iv = p2; fv = p3; gv = a2; ov = a3; row = rbase + 8; }
                int n0 = nbase + warpn * 32 + nf * 8 + pairq * 4;
                float4 bs = *(const float4*)(g_bias + z * NG + n0);
                iv += bs.x; fv += bs.y; gv += bs.z; ov += bs.w;

                int b  = mbase + warpm * 64 + mf * 16 + row;
                int j  = n0 >> 2;
                size_t co = (size_t)b * HID_ + j;
                float cold = cpz[co];
                float cn = sigf_(fv) * cold + sigf_(iv) * tanhf(gv);
                float hn = sigf_(ov) * tanhf(cn);
                cpz[co] = cn;
                __half hh = __float2half_rn(hn);
                dst0[(size_t)b * KP2 + j] = hh;
                if (z == 1) dst1[(size_t)b * KP2 + j] = hh;
                if (z == 2) {
                    size_t ho = ((size_t)t * B_ + b) * HID_ + j;
                    g_histH[ho] = hh;
                    g_histL[ho] = __float2half_rn(hn - __half2float(hh));
                }
            }
        }
        asm volatile("cp.async.wait_group 0;" ::: "memory");
        __syncthreads();   // smem safe to reuse for next job
    }
}

// ---------------- feedback: x_{t+1} = h2[t] @ Wd^T + bd (free-run input) ----
__global__ __launch_bounds__(256) void feedback_kernel(int t, const float* __restrict__ bd) {
    __shared__ float sh[4][HID_];
    const int tid = threadIdx.x, bg = blockIdx.x;
    for (int i = tid; i < 4 * HID_; i += 256) {
        size_t ho = ((size_t)t * B_ + bg * 4 + (i >> 10)) * HID_ + (i & 1023);
        sh[i >> 10][i & 1023] = __half2float(g_histH[ho]) + __half2float(g_histL[ho]);
    }
    __syncthreads();
    const int n = tid;
    if (n >= INF) return;
    float acc[4] = {0, 0, 0, 0};
    for (int k = 0; k < HID_; k += 4) {
#pragma unroll
        for (int kk = 0; kk < 4; kk++) {
            float w = g_Bd[(size_t)(k + kk) * INF + n];
#pragma unroll
            for (int r = 0; r < 4; r++) acc[r] = fmaf(sh[r][k + kk], w, acc[r]);
        }
    }
#pragma unroll
    for (int r = 0; r < 4; r++) {
        float v = acc[r] + bd[n];
        g_Ax[(size_t)(t + 1) * (B_ * 256) + (size_t)(bg * 4 + r) * 256 + n] = __float2half_rn(v);
    }
}

// ---------------- final dense via HMMA (3-term fp16, split hist + split Wd) ----
__global__ void __launch_bounds__(256, 1) dense_kernel(float* __restrict__ out,
                                                       const float* __restrict__ bd) {
    extern __shared__ char dynsmem[];
    const int tid = threadIdx.x;
    const int warp = tid >> 5, lane = tid & 31;
    const int warpm = warp >> 2, warpn = warp & 3;
    const int mbase = (blockIdx.x >> 1) * 128;
    const int nbase = (blockIdx.x & 1) * 128;
    const int nch = HID_ >> 5;  // 32
    const uint32_t sbase = smem_u32(dynsmem);

    auto issue = [&](int ch) {
        if (ch < nch) {
            const uint32_t sb = sbase + (ch % NSTAGE) * DSTAGEB;
            const int k0 = ch << 5;
#pragma unroll
            for (int it = 0; it < 8; it++) {
                int s = it * 256 + tid;
                int tile = s >> 9;
                int r  = (s & 511) >> 2;
                int c4 = s & 3;
                uint32_t d = sb + tile * TILEB + r * PITCH + c4 * 16;
                const __half* gp;
                if (tile == 0)      gp = g_histH + (size_t)(mbase + r) * HID_ + k0 + c4 * 8;
                else if (tile == 1) gp = g_histL + (size_t)(mbase + r) * HID_ + k0 + c4 * 8;
                else if (tile == 2) gp = g_BdH   + (size_t)(nbase + r) * HID_ + k0 + c4 * 8;
                else                gp = g_BdL   + (size_t)(nbase + r) * HID_ + k0 + c4 * 8;
                cp16(d, gp);
            }
        }
        cp_commit();
    };

    float acc[4][4][4];
#pragma unroll
    for (int mf = 0; mf < 4; mf++)
#pragma unroll
        for (int nf = 0; nf < 4; nf++)
#pragma unroll
            for (int i = 0; i < 4; i++) acc[mf][nf][i] = 0.0f;

    issue(0); issue(1);
    for (int ch = 0; ch < nch; ch++) {
        asm volatile("cp.async.wait_group 1;" ::: "memory");
        __syncthreads();
        issue(ch + 2);
        const uint32_t sb = sbase + (ch % NSTAGE) * DSTAGEB;
#pragma unroll
        for (int kk = 0; kk < 2; kk++) {
            uint32_t ah[4][4], al[4][4];
#pragma unroll
            for (int mf = 0; mf < 4; mf++) {
                uint32_t addr = sb + (uint32_t)(warpm * 64 + mf * 16 + (lane & 15)) * PITCH
                              + kk * 32 + (lane >> 4) * 16;
                ldm_x4(ah[mf], addr);
                ldm_x4(al[mf], addr + TILEB);
            }
            uint32_t bh[2][4], bl[2][4];
#pragma unroll
            for (int nf2 = 0; nf2 < 2; nf2++) {
                int nrow = warpn * 32 + nf2 * 16 + (lane & 7) + ((lane >> 4) << 3);
                uint32_t addr = sb + 2 * TILEB + (uint32_t)nrow * PITCH
                              + kk * 32 + ((lane >> 3) & 1) * 16;
                ldm_x4(bh[nf2], addr);
                ldm_x4(bl[nf2], addr + TILEB);
            }
#pragma unroll
            for (int mf = 0; mf < 4; mf++)
#pragma unroll
                for (int nf = 0; nf < 4; nf++) {
                    const int nf2 = nf >> 1, h = nf & 1;
                    uint32_t b0h = bh[nf2][h * 2], b1h = bh[nf2][h * 2 + 1];
                    uint32_t b0l = bl[nf2][h * 2], b1l = bl[nf2][h * 2 + 1];
                    mma16816(acc[mf][nf], ah[mf], b0h, b1h);
                    mma16816(acc[mf][nf], ah[mf], b0l, b1l);
                    mma16816(acc[mf][nf], al[mf], b0h, b1h);
                }
        }
    }

    // epilogue: native c-frag layout -> out[b][t*227+n]
    const int rbase = lane >> 2;
    const int cbase = (lane & 3) * 2;
#pragma unroll
    for (int mf = 0; mf < 4; mf++) {
#pragma unroll
        for (int nf = 0; nf < 4; nf++) {
#pragma unroll
            for (int i = 0; i < 4; i++) {
                int row = mbase + warpm * 64 + mf * 16 + rbase + (i >> 1) * 8;
                int n   = nbase + warpn * 32 + nf * 8 + cbase + (i & 1);
                if (n < INF) {
                    int tt = row >> 8, bb = row & 255;
                    out[(size_t)bb * (T_ * INF) + (size_t)tt * INF + n] =
                        acc[mf][nf][i] + bd[n];
                }
            }
        }
    }
}

// ---------------- launch ----------------
extern "C" void kernel_launch(void* const* d_in, const int* in_sizes, int n_in,
                              void* d_out, int out_size) {
    (void)in_sizes; (void)n_in; (void)out_size;
    const float* rs   = (const float*)d_in[0];
    const float* Wih1 = (const float*)d_in[1];
    const float* Whh1 = (const float*)d_in[2];
    const float* bih1 = (const float*)d_in[3];
    const float* bhh1 = (const float*)d_in[4];
    const float* Wih2 = (const float*)d_in[5];
    const float* Whh2 = (const float*)d_in[6];
    const float* bih2 = (const float*)d_in[7];
    const float* bhh2 = (const float*)d_in[8];
    const float* Wih3 = (const float*)d_in[9];
    const float* Whh3 = (const float*)d_in[10];
    const float* bih3 = (const float*)d_in[11];
    const float* bhh3 = (const float*)d_in[12];
    const float* Wd   = (const float*)d_in[13];
    const float* bd   = (const float*)d_in[14];
    float* out = (float*)d_out;

    cudaFuncSetAttribute(gates_kernel, cudaFuncAttributeMaxDynamicSharedMemorySize, GSMEM);
    cudaFuncSetAttribute(dense_kernel, cudaFuncAttributeMaxDynamicSharedMemorySize, DSMEM_D);

    k_zero<<<2048, 256>>>();
    k_setup<<<4096, 256>>>(Wih1, Whh1, Wih2, Whh2, Wih3, Whh3,
                           bih1, bhh1, bih2, bhh2, bih3, bhh3);
    k_setup_bd<<<(256 * HID_ + 255) / 256, 256>>>(Wd);
    stage_x<<<(T_ * B_ * 256) / 256, 256>>>(rs);

    for (int t = 0; t < T_; t++) {
        gates_kernel<<<152, 256, GSMEM>>>(t);
        if (t < T_ - 1 && ((t + 1) % 10) >= 5)
            feedback_kernel<<<64, 256>>>(t, bd);   // free-run input for step t+1
    }
    dense_kernel<<<400, 256, DSMEM_D>>>(out, bd);
}

// round 12
// speedup vs baseline: 2.7112x; 1.4485x over previous
#include <cuda_runtime.h>
#include <cuda_fp16.h>
#include <math.h>
#include <stdint.h>

// ---------------- problem constants ----------------
#define B_    256
#define T_    100
#define INF   227
#define HID_  1024
#define NG    4096          // 4*HID
#define KP1   1280          // layer1 K: [h(1024) | x(227 pad 256)]
#define KP2   2048
#define SL    (B_*HID_)

#define W1SZ  (NG*KP1)
#define W2SZ  (NG*KP2)
#define WTOT  (W1SZ + 2*W2SZ)
#define A2SZ  (B_*KP2)      // one [h|h] activation panel
#define APAR  (2*A2SZ)      // layer2 + layer3 panels per parity

// gates tiles: CTA 64x128, K-chunk 64, pitch 144B (4r mod 32 banks, conflict-free)
#define PITCHG  144
#define TILEA   (64*PITCHG)      // 9216
#define TILEBW  (128*PITCHG)     // 18432
#define GSTAGEB (TILEA+TILEBW)   // 27648
#define NSTAGE  3
#define GSMEM   (NSTAGE*GSTAGEB) // 82944

// dense tiles (128x128, K-chunk 32, pitch 80 — as R11)
#define PITCH2  80
#define TILE2   (128*PITCH2)     // 10240
#define DSTAGEB (4*TILE2)        // 40960
#define DSMEM_D (NSTAGE*DSTAGEB) // 122880

#define NCTA    148

// ---------------- static device scratch ----------------
__device__ __align__(16) __half g_Wh[WTOT];     // weights fp16, [n][k]
__device__ __align__(16) __half g_A [2*APAR];   // [parity][L2 panel | L3 panel]
__device__ __align__(16) __half g_Ax[(size_t)T_*B_*256]; // per-step x frames
__device__ __align__(16) float g_bias[3*NG];    // bih+bhh, ifgo quads
__device__ __align__(16) __half g_BdH[256*HID_];// Wd fp16 hi, [n][k], rows>=227 zero
__device__ __align__(16) __half g_BdL[256*HID_];// Wd fp16 lo (dense only)
__device__ __align__(16) float g_c[3*SL];       // cell states fp32
__device__ __align__(16) __half g_histH[(size_t)T_*SL]; // h2 history hi
__device__ __align__(16) __half g_histL[(size_t)T_*SL]; // h2 history lo
__device__ unsigned g_ticket[T_];               // per-step job tickets
__device__ unsigned g_z2done[T_];               // per-step z2 job completion count

__device__ __forceinline__ float sigf_(float x) { return 1.0f / (1.0f + expf(-x)); }

// ---------------- PTX helpers (plain sm_80+ features only) ----------------
__device__ __forceinline__ uint32_t smem_u32(const void* p) {
    uint32_t a;
    asm("{ .reg .u64 t; cvta.to.shared.u64 t, %1; cvt.u32.u64 %0, t; }" : "=r"(a) : "l"(p));
    return a;
}
__device__ __forceinline__ void cp16(uint32_t d, const void* g) {
    asm volatile("cp.async.cg.shared.global [%0], [%1], 16;" :: "r"(d), "l"(g) : "memory");
}
__device__ __forceinline__ void cp_commit() {
    asm volatile("cp.async.commit_group;" ::: "memory");
}
__device__ __forceinline__ void ldm_x4(uint32_t* r, uint32_t a) {
    asm volatile("ldmatrix.sync.aligned.m8n8.x4.shared.b16 {%0,%1,%2,%3}, [%4];"
                 : "=r"(r[0]), "=r"(r[1]), "=r"(r[2]), "=r"(r[3]) : "r"(a));
}
__device__ __forceinline__ void mma16816(float* c, const uint32_t* a, uint32_t b0, uint32_t b1) {
    asm volatile("mma.sync.aligned.m16n8k16.row.col.f32.f16.f16.f32 "
                 "{%0,%1,%2,%3}, {%4,%5,%6,%7}, {%8,%9}, {%0,%1,%2,%3};"
                 : "+f"(c[0]), "+f"(c[1]), "+f"(c[2]), "+f"(c[3])
                 : "r"(a[0]), "r"(a[1]), "r"(a[2]), "r"(a[3]), "r"(b0), "r"(b1));
}

// ---------------- zero mutable state each replay ----------------
__global__ void k_zero() {
    const size_t CW = (size_t)3 * SL;     // g_c floats
    const size_t AW = (size_t)APAR;       // g_A (2*APAR halfs = APAR words)
    const size_t N  = CW + AW + 2 * T_;
    for (size_t i = (size_t)blockIdx.x * blockDim.x + threadIdx.x; i < N;
         i += (size_t)gridDim.x * blockDim.x) {
        if (i < CW)                g_c[i] = 0.0f;
        else if (i < CW + AW)      ((uint32_t*)g_A)[i - CW] = 0u;
        else if (i < CW + AW + T_) g_ticket[i - CW - AW] = 0u;
        else                       g_z2done[i - CW - AW - T_] = 0u;
    }
}

// ---------------- weight reorder + fp16 ----------------
// Layer1 K order: [h (k 0..1023) | x (k 1024..1250) | pad].
__global__ void k_setup(const float* __restrict__ Wih1, const float* __restrict__ Whh1,
                        const float* __restrict__ Wih2, const float* __restrict__ Whh2,
                        const float* __restrict__ Wih3, const float* __restrict__ Whh3,
                        const float* __restrict__ bih1, const float* __restrict__ bhh1,
                        const float* __restrict__ bih2, const float* __restrict__ bhh2,
                        const float* __restrict__ bih3, const float* __restrict__ bhh3) {
    const long TOT = (long)WTOT + 3L * NG;
    for (long idx = (long)blockIdx.x * blockDim.x + threadIdx.x; idx < TOT;
         idx += (long)gridDim.x * blockDim.x) {
        long r = idx;
        if (r < (long)WTOT) {
            int z, n, k;
            if (r < W1SZ)              { z = 0; n = (int)(r / KP1); k = (int)(r % KP1); }
            else if (r < W1SZ + W2SZ)  { long q = r - W1SZ; z = 1; n = (int)(q / KP2); k = (int)(q % KP2); }
            else                       { long q = r - W1SZ - W2SZ; z = 2; n = (int)(q / KP2); k = (int)(q % KP2); }
            int R = (n & 3) * HID_ + (n >> 2);   // ifgo-quad reorder
            float w = 0.0f;
            if (z == 0) {
                if (k < HID_)           w = Whh1[(size_t)R * HID_ + k];
                else if (k < HID_+INF)  w = Wih1[(size_t)R * INF + (k - HID_)];
            } else if (z == 1) {
                w = (k < HID_) ? Wih2[(size_t)R * HID_ + k] : Whh2[(size_t)R * HID_ + (k - HID_)];
            } else {
                w = (k < HID_) ? Wih3[(size_t)R * HID_ + k] : Whh3[(size_t)R * HID_ + (k - HID_)];
            }
            g_Wh[r] = __float2half_rn(w);
            continue;
        }
        r -= WTOT;
        {
            int L = (int)(r / NG), n = (int)(r % NG);
            int R = (n & 3) * HID_ + (n >> 2);
            float v = (L == 0) ? bih1[R] + bhh1[R]
                    : (L == 1) ? bih2[R] + bhh2[R]
                               : bih3[R] + bhh3[R];
            g_bias[r] = v;
        }
    }
}

// Wd fp16 hi/lo [n][k] padded to 256 rows
__global__ void k_setup_bd(const float* __restrict__ Wd) {
    int i = blockIdx.x * blockDim.x + threadIdx.x;
    if (i >= 256 * HID_) return;
    int n = i / HID_, k = i % HID_;
    float w = (n < INF) ? Wd[(size_t)n * HID_ + k] : 0.0f;
    __half hi = __float2half_rn(w);
    g_BdH[i] = hi;
    g_BdL[i] = __float2half_rn(w - __half2float(hi));
}

// ---------------- stage ALL x frames upfront (teacher frames + zero pads) ----
__global__ void stage_x(const float* __restrict__ rs) {
    long i = (long)blockIdx.x * blockDim.x + threadIdx.x;
    if (i >= (long)T_ * B_ * 256) return;
    int n = (int)(i & 255);
    int b = (int)((i >> 8) & 255);
    int t = (int)(i >> 16);
    float v = 0.0f;
    if (n < INF && (t % 10) < 5)
        v = rs[(size_t)b * (T_ * INF) + (size_t)t * INF + n];
    g_Ax[i] = __float2half_rn(v);
}

// ---------------- persistent fused HMMA step kernel ----------------
// 148 persistent CTAs, atomic ticket queue. Jobs per step:
//   tickets [0,256): z1/z2 gate tiles (32 K64-chunks)   — interleaved z1/z2
//   tickets [256,384): z0 gate tiles (20 chunks, [h0|x])
//   tickets [384,392): feedback tiles x(t+1)=h2(t)@Wd^T+bd (16 chunks),
//                      spin-guarded on all 128 z2 jobs done (present only when
//                      step t+1 runs free). x consumed by NEXT launch -> no race.
// CTA tile 64x128, 8 warps (2M x 4N), warp tile 32x32, 3-stage cp.async.
__global__ void __launch_bounds__(256, 1) gates_kernel(int t, int njobs,
                                                       const float* __restrict__ bd) {
    extern __shared__ char dynsmem[];
    __shared__ int s_job;
    const int tid = threadIdx.x;
    const int warp = tid >> 5, lane = tid & 31;
    const int warpm = warp >> 2, warpn = warp & 3;
    const int p = t & 1, pn = p ^ 1;
    const uint32_t sbase = smem_u32(dynsmem);
    const __half* __restrict__ Apar = g_A + (size_t)p * APAR;

    for (;;) {
        if (tid == 0) s_job = (int)atomicAdd(&g_ticket[t], 1u);
        __syncthreads();
        const int jid = s_job;
        if (jid >= njobs) return;

        // ---- decode job ----
        int typ, z = 0, mbase, nbase, nch, asplit;
        const __half *ap0, *ap1 = nullptr, *bp;
        int as0, as1 = 0, bstr;
        if (jid < 256) {                       // z1 / z2
            typ = 0; z = 1 + (jid & 1);
            int idx = jid >> 1;
            mbase = (idx & 3) * 64; nbase = (idx >> 2) * 128;
            nch = 32; asplit = 32;
            ap0 = Apar + ((z == 2) ? (size_t)A2SZ : 0); as0 = KP2;
            bp  = g_Wh + ((z == 1) ? (size_t)W1SZ : (size_t)(W1SZ + W2SZ)); bstr = KP2;
        } else if (jid < 384) {                // z0: [h0 | x]
            typ = 0; z = 0;
            int idx = jid - 256;
            mbase = (idx & 3) * 64; nbase = (idx >> 2) * 128;
            nch = 20; asplit = 16;
            ap0 = Apar; as0 = KP2;
            ap1 = g_Ax + (size_t)t * (B_ * 256); as1 = 256;
            bp  = g_Wh; bstr = KP1;
        } else {                               // feedback: x(t+1) = h2(t)@Wd^T+bd
            typ = 1;
            int idx = jid - 384;
            mbase = (idx & 3) * 64; nbase = (idx >> 2) * 128;
            nch = 16; asplit = 16;
            ap0 = g_histH + (size_t)t * SL; as0 = HID_;
            bp  = g_BdH; bstr = HID_;
            // wait for all 128 z2 jobs of this step
            if (tid == 0) { while (atomicAdd(&g_z2done[t], 0u) < 128u) {} }
            __syncthreads();
            __threadfence();
        }

        // ---- async stage loader: 1536 x 16B per stage, 6 per thread ----
        auto issue = [&](int ch) {
            if (ch < nch) {
                const uint32_t sb = sbase + (ch % NSTAGE) * GSTAGEB;
                const int k0 = ch << 6;
#pragma unroll
                for (int it = 0; it < 6; it++) {
                    int s = it * 256 + tid;           // 0..1535
                    if (s < 512) {                     // A tile: 64 rows x 8 c16
                        int r = s >> 3, c4 = s & 7;
                        const __half* gp = (ch < asplit)
                            ? ap0 + (size_t)(mbase + r) * as0 + k0 + c4 * 8
                            : ap1 + (size_t)(mbase + r) * as1 + (k0 - (asplit << 6)) + c4 * 8;
                        cp16(sbase + (ch % NSTAGE) * GSTAGEB + r * PITCHG + c4 * 16, gp);
                    } else {                           // B tile: 128 rows x 8 c16
                        int sB = s - 512; int r = sB >> 3, c4 = sB & 7;
                        cp16(sb + TILEA + r * PITCHG + c4 * 16,
                             bp + (size_t)(nbase + r) * bstr + k0 + c4 * 8);
                    }
                }
            }
            cp_commit();
        };

        float acc[2][4][4];
#pragma unroll
        for (int mf = 0; mf < 2; mf++)
#pragma unroll
            for (int nf = 0; nf < 4; nf++)
#pragma unroll
                for (int i = 0; i < 4; i++) acc[mf][nf][i] = 0.0f;

        issue(0); issue(1);
        for (int ch = 0; ch < nch; ch++) {
            asm volatile("cp.async.wait_group 1;" ::: "memory");
            __syncthreads();
            issue(ch + 2);
            const uint32_t sb = sbase + (ch % NSTAGE) * GSTAGEB;
#pragma unroll
            for (int kk = 0; kk < 4; kk++) {
                uint32_t ah[2][4];
#pragma unroll
                for (int mf = 0; mf < 2; mf++) {
                    uint32_t addr = sb + (uint32_t)(warpm * 32 + mf * 16 + (lane & 15)) * PITCHG
                                  + kk * 32 + (lane >> 4) * 16;
                    ldm_x4(ah[mf], addr);
                }
                uint32_t bh[2][4];
#pragma unroll
                for (int nf2 = 0; nf2 < 2; nf2++) {
                    int nrow = warpn * 32 + nf2 * 16 + (lane & 7) + ((lane >> 4) << 3);
                    uint32_t addr = sb + TILEA + (uint32_t)nrow * PITCHG
                                  + kk * 32 + ((lane >> 3) & 1) * 16;
                    ldm_x4(bh[nf2], addr);
                }
#pragma unroll
                for (int mf = 0; mf < 2; mf++)
#pragma unroll
                    for (int nf = 0; nf < 4; nf++)
                        mma16816(acc[mf][nf], ah[mf],
                                 bh[nf >> 1][(nf & 1) * 2], bh[nf >> 1][(nf & 1) * 2 + 1]);
            }
        }

        if (typ == 0) {
            // ---- LSTM epilogue: shuffle c-frags into (i,f,g,o) quads ----
            const int c     = lane & 3;
            const int pairq = c >> 1;
            const int pos   = c & 1;
            const int rbase = lane >> 2;

            float* cpz = g_c + (size_t)z * SL;
            __half* dst0; __half* dst1 = nullptr;
            if (z == 0)      { dst0 = g_A + (size_t)pn * APAR; }
            else if (z == 1) { dst0 = g_A + (size_t)pn * APAR + 1024;
                               dst1 = g_A + (size_t)pn * APAR + A2SZ; }
            else             { dst0 = g_A + (size_t)pn * APAR + A2SZ + 1024; }

#pragma unroll
            for (int mf = 0; mf < 2; mf++) {
#pragma unroll
                for (int nf = 0; nf < 4; nf++) {
                    float a0 = acc[mf][nf][0], a1 = acc[mf][nf][1];
                    float a2 = acc[mf][nf][2], a3 = acc[mf][nf][3];
                    float p0 = __shfl_xor_sync(0xffffffffu, a0, 1);
                    float p1 = __shfl_xor_sync(0xffffffffu, a1, 1);
                    float p2 = __shfl_xor_sync(0xffffffffu, a2, 1);
                    float p3 = __shfl_xor_sync(0xffffffffu, a3, 1);
                    float iv, fv, gv, ov; int row;
                    if (pos == 0) { iv = a0; fv = a1; gv = p0; ov = p1; row = rbase; }
                    else          { iv = p2; fv = p3; gv = a2; ov = a3; row = rbase + 8; }
                    int n0 = nbase + warpn * 32 + nf * 8 + pairq * 4;
                    float4 bs = *(const float4*)(g_bias + z * NG + n0);
                    iv += bs.x; fv += bs.y; gv += bs.z; ov += bs.w;

                    int b = mbase + warpm * 32 + mf * 16 + row;
                    int j = n0 >> 2;
                    size_t co = (size_t)b * HID_ + j;
                    float cold = cpz[co];
                    float cn = sigf_(fv) * cold + sigf_(iv) * tanhf(gv);
                    float hn = sigf_(ov) * tanhf(cn);
                    cpz[co] = cn;
                    __half hh = __float2half_rn(hn);
                    dst0[(size_t)b * KP2 + j] = hh;
                    if (z == 1) dst1[(size_t)b * KP2 + j] = hh;
                    if (z == 2) {
                        size_t ho = ((size_t)t * B_ + b) * HID_ + j;
                        g_histH[ho] = hh;
                        g_histL[ho] = __float2half_rn(hn - __half2float(hh));
                    }
                }
            }
            if (z == 2) {
                __threadfence();
                __syncthreads();
                if (tid == 0) atomicAdd(&g_z2done[t], 1u);
            }
        } else {
            // ---- feedback epilogue: x(t+1) = acc + bd, fp16 into g_Ax ----
            const int rbase = lane >> 2;
            const int cbase = (lane & 3) * 2;
            __half* xd = g_Ax + (size_t)(t + 1) * (B_ * 256);
#pragma unroll
            for (int mf = 0; mf < 2; mf++) {
#pragma unroll
                for (int nf = 0; nf < 4; nf++) {
#pragma unroll
                    for (int i = 0; i < 4; i++) {
                        int row = mbase + warpm * 32 + mf * 16 + rbase + (i >> 1) * 8;
                        int n   = nbase + warpn * 32 + nf * 8 + cbase + (i & 1);
                        if (n < INF)
                            xd[(size_t)row * 256 + n] =
                                __float2half_rn(acc[mf][nf][i] + bd[n]);
                    }
                }
            }
        }
        asm volatile("cp.async.wait_group 0;" ::: "memory");
        __syncthreads();   // smem safe to reuse for next job
    }
}

// ---------------- final dense via HMMA (3-term fp16, split hist + split Wd) ----
__global__ void __launch_bounds__(256, 1) dense_kernel(float* __restrict__ out,
                                                       const float* __restrict__ bd) {
    extern __shared__ char dynsmem[];
    const int tid = threadIdx.x;
    const int warp = tid >> 5, lane = tid & 31;
    const int warpm = warp >> 2, warpn = warp & 3;
    const int mbase = (blockIdx.x >> 1) * 128;
    const int nbase = (blockIdx.x & 1) * 128;
    const int nch = HID_ >> 5;  // 32
    const uint32_t sbase = smem_u32(dynsmem);

    auto issue = [&](int ch) {
        if (ch < nch) {
            const uint32_t sb = sbase + (ch % NSTAGE) * DSTAGEB;
            const int k0 = ch << 5;
#pragma unroll
            for (int it = 0; it < 8; it++) {
                int s = it * 256 + tid;
                int tile = s >> 9;
                int r  = (s & 511) >> 2;
                int c4 = s & 3;
                uint32_t d = sb + tile * TILE2 + r * PITCH2 + c4 * 16;
                const __half* gp;
                if (tile == 0)      gp = g_histH + (size_t)(mbase + r) * HID_ + k0 + c4 * 8;
                else if (tile == 1) gp = g_histL + (size_t)(mbase + r) * HID_ + k0 + c4 * 8;
                else if (tile == 2) gp = g_BdH   + (size_t)(nbase + r) * HID_ + k0 + c4 * 8;
                else                gp = g_BdL   + (size_t)(nbase + r) * HID_ + k0 + c4 * 8;
                cp16(d, gp);
            }
        }
        cp_commit();
    };

    float acc[4][4][4];
#pragma unroll
    for (int mf = 0; mf < 4; mf++)
#pragma unroll
        for (int nf = 0; nf < 4; nf++)
#pragma unroll
            for (int i = 0; i < 4; i++) acc[mf][nf][i] = 0.0f;

    issue(0); issue(1);
    for (int ch = 0; ch < nch; ch++) {
        asm volatile("cp.async.wait_group 1;" ::: "memory");
        __syncthreads();
        issue(ch + 2);
        const uint32_t sb = sbase + (ch % NSTAGE) * DSTAGEB;
#pragma unroll
        for (int kk = 0; kk < 2; kk++) {
            uint32_t ah[4][4], al[4][4];
#pragma unroll
            for (int mf = 0; mf < 4; mf++) {
                uint32_t addr = sb + (uint32_t)(warpm * 64 + mf * 16 + (lane & 15)) * PITCH2
                              + kk * 32 + (lane >> 4) * 16;
                ldm_x4(ah[mf], addr);
                ldm_x4(al[mf], addr + TILE2);
            }
            uint32_t bh[2][4], bl[2][4];
#pragma unroll
            for (int nf2 = 0; nf2 < 2; nf2++) {
                int nrow = warpn * 32 + nf2 * 16 + (lane & 7) + ((lane >> 4) << 3);
                uint32_t addr = sb + 2 * TILE2 + (uint32_t)nrow * PITCH2
                              + kk * 32 + ((lane >> 3) & 1) * 16;
                ldm_x4(bh[nf2], addr);
                ldm_x4(bl[nf2], addr + TILE2);
            }
#pragma unroll
            for (int mf = 0; mf < 4; mf++)
#pragma unroll
                for (int nf = 0; nf < 4; nf++) {
                    const int nf2 = nf >> 1, h = nf & 1;
                    uint32_t b0h = bh[nf2][h * 2], b1h = bh[nf2][h * 2 + 1];
                    uint32_t b0l = bl[nf2][h * 2], b1l = bl[nf2][h * 2 + 1];
                    mma16816(acc[mf][nf], ah[mf], b0h, b1h);
                    mma16816(acc[mf][nf], ah[mf], b0l, b1l);
                    mma16816(acc[mf][nf], al[mf], b0h, b1h);
                }
        }
    }

    const int rbase = lane >> 2;
    const int cbase = (lane & 3) * 2;
#pragma unroll
    for (int mf = 0; mf < 4; mf++) {
#pragma unroll
        for (int nf = 0; nf < 4; nf++) {
#pragma unroll
            for (int i = 0; i < 4; i++) {
                int row = mbase + warpm * 64 + mf * 16 + rbase + (i >> 1) * 8;
                int n   = nbase + warpn * 32 + nf * 8 + cbase + (i & 1);
                if (n < INF) {
                    int tt = row >> 8, bb = row & 255;
                    out[(size_t)bb * (T_ * INF) + (size_t)tt * INF + n] =
                        acc[mf][nf][i] + bd[n];
                }
            }
        }
    }
}

// ---------------- launch ----------------
extern "C" void kernel_launch(void* const* d_in, const int* in_sizes, int n_in,
                              void* d_out, int out_size) {
    (void)in_sizes; (void)n_in; (void)out_size;
    const float* rs   = (const float*)d_in[0];
    const float* Wih1 = (const float*)d_in[1];
    const float* Whh1 = (const float*)d_in[2];
    const float* bih1 = (const float*)d_in[3];
    const float* bhh1 = (const float*)d_in[4];
    const float* Wih2 = (const float*)d_in[5];
    const float* Whh2 = (const float*)d_in[6];
    const float* bih2 = (const float*)d_in[7];
    const float* bhh2 = (const float*)d_in[8];
    const float* Wih3 = (const float*)d_in[9];
    const float* Whh3 = (const float*)d_in[10];
    const float* bih3 = (const float*)d_in[11];
    const float* bhh3 = (const float*)d_in[12];
    const float* Wd   = (const float*)d_in[13];
    const float* bd   = (const float*)d_in[14];
    float* out = (float*)d_out;

    cudaFuncSetAttribute(gates_kernel, cudaFuncAttributeMaxDynamicSharedMemorySize, GSMEM);
    cudaFuncSetAttribute(dense_kernel, cudaFuncAttributeMaxDynamicSharedMemorySize, DSMEM_D);

    k_zero<<<2048, 256>>>();
    k_setup<<<4096, 256>>>(Wih1, Whh1, Wih2, Whh2, Wih3, Whh3,
                           bih1, bhh1, bih2, bhh2, bih3, bhh3);
    k_setup_bd<<<(256 * HID_ + 255) / 256, 256>>>(Wd);
    stage_x<<<(T_ * B_ * 256) / 256, 256>>>(rs);

    for (int t = 0; t < T_; t++) {
        int nextfb = (t < T_ - 1) && (((t + 1) % 10) >= 5);
        int njobs = 384 + (nextfb ? 8 : 0);
        gates_kernel<<<NCTA, 256, GSMEM>>>(t, njobs, bd);
    }
    dense_kernel<<<400, 256, DSMEM_D>>>(out, bd);
}

// round 13
// speedup vs baseline: 3.2376x; 1.1942x over previous
#include <cuda_runtime.h>
#include <cuda_fp16.h>
#include <math.h>
#include <stdint.h>

// ---------------- problem constants ----------------
#define B_    256
#define T_    100
#define INF   227
#define HID_  1024
#define NG    4096          // 4*HID
#define KP1   1280          // layer1 K: [h(1024) | x(227 pad 256)]
#define KP2   2048
#define SL    (B_*HID_)

#define W1SZ  (NG*KP1)
#define W2SZ  (NG*KP2)
#define WTOT  (W1SZ + 2*W2SZ)
#define A2SZ  (B_*KP2)      // one [h|h] activation panel
#define APAR  (2*A2SZ)      // layer2 + layer3 panels per parity

// gates tiles: CTA 64x128, K-chunk 64, pitch 144B (conflict-free ldmatrix)
#define PITCHG  144
#define TILEA   (64*PITCHG)      // 9216
#define TILEBW  (128*PITCHG)     // 18432
#define GSTAGEB (TILEA+TILEBW)   // 27648
#define NSTAGE  3
#define GSMEM   (NSTAGE*GSTAGEB) // 82944

// dense tiles (128x128, K-chunk 32, pitch 80)
#define PITCH2  80
#define TILE2   (128*PITCH2)     // 10240
#define DSTAGEB (4*TILE2)        // 40960
#define DSMEM_D (NSTAGE*DSTAGEB) // 122880

#define NCTA    148

// ---------------- static device scratch ----------------
__device__ __align__(16) __half g_Wh[WTOT];     // weights fp16, [n][k]
__device__ __align__(16) __half g_A [2*APAR];   // [parity][L2 panel | L3 panel]
__device__ __align__(16) __half g_Ax[(size_t)T_*B_*256]; // per-step x frames
__device__ __align__(16) float g_bias[3*NG];    // bih+bhh, ifgo quads
__device__ __align__(16) __half g_BdH[256*HID_];// Wd fp16 hi, [n][k], rows>=227 zero
__device__ __align__(16) __half g_BdL[256*HID_];// Wd fp16 lo (dense only)
__device__ __align__(16) float g_c[3*SL];       // cell states fp32
__device__ __align__(16) __half g_histH[(size_t)T_*SL]; // h2 history hi
__device__ __align__(16) __half g_histL[(size_t)T_*SL]; // h2 history lo
__device__ unsigned g_ticket[T_];               // per-step job tickets
__device__ unsigned g_cnt[T_][3][4];            // (step, layer, mtile) done counts
__device__ unsigned g_fbdone[T_];               // per-step feedback job done count

__device__ __forceinline__ float sigf_(float x) { return 1.0f / (1.0f + expf(-x)); }

// ---------------- PTX helpers (plain sm_80+ features only) ----------------
__device__ __forceinline__ uint32_t smem_u32(const void* p) {
    uint32_t a;
    asm("{ .reg .u64 t; cvta.to.shared.u64 t, %1; cvt.u32.u64 %0, t; }" : "=r"(a) : "l"(p));
    return a;
}
__device__ __forceinline__ void cp16(uint32_t d, const void* g) {
    asm volatile("cp.async.cg.shared.global [%0], [%1], 16;" :: "r"(d), "l"(g) : "memory");
}
__device__ __forceinline__ void cp_commit() {
    asm volatile("cp.async.commit_group;" ::: "memory");
}
__device__ __forceinline__ void ldm_x4(uint32_t* r, uint32_t a) {
    asm volatile("ldmatrix.sync.aligned.m8n8.x4.shared.b16 {%0,%1,%2,%3}, [%4];"
                 : "=r"(r[0]), "=r"(r[1]), "=r"(r[2]), "=r"(r[3]) : "r"(a));
}
__device__ __forceinline__ void mma16816(float* c, const uint32_t* a, uint32_t b0, uint32_t b1) {
    asm volatile("mma.sync.aligned.m16n8k16.row.col.f32.f16.f16.f32 "
                 "{%0,%1,%2,%3}, {%4,%5,%6,%7}, {%8,%9}, {%0,%1,%2,%3};"
                 : "+f"(c[0]), "+f"(c[1]), "+f"(c[2]), "+f"(c[3])
                 : "r"(a[0]), "r"(a[1]), "r"(a[2]), "r"(a[3]), "r"(b0), "r"(b1));
}
// L2-coherent spin (L1 not flushed inside a persistent launch)
__device__ __forceinline__ void spin_ge(const unsigned* p, unsigned tgt) {
    for (;;) {
        unsigned v;
        asm volatile("ld.global.cg.u32 %0, [%1];" : "=r"(v) : "l"(p));
        if (v >= tgt) return;
        __nanosleep(64);
    }
}

// ---------------- zero mutable state each replay ----------------
__global__ void k_zero() {
    const size_t CW = (size_t)3 * SL;     // g_c floats
    const size_t AW = (size_t)APAR;       // g_A (2*APAR halfs = APAR words)
    const size_t N  = CW + AW + 14 * T_;  // + ticket(1) + cnt(12) + fbdone(1) per step
    for (size_t i = (size_t)blockIdx.x * blockDim.x + threadIdx.x; i < N;
         i += (size_t)gridDim.x * blockDim.x) {
        if (i < CW)                      g_c[i] = 0.0f;
        else if (i < CW + AW)            ((uint32_t*)g_A)[i - CW] = 0u;
        else if (i < CW + AW + T_)       g_ticket[i - CW - AW] = 0u;
        else if (i < CW + AW + 13 * T_)  ((unsigned*)g_cnt)[i - CW - AW - T_] = 0u;
        else                             g_fbdone[i - CW - AW - 13 * T_] = 0u;
    }
}

// ---------------- weight reorder + fp16 ----------------
// Layer1 K order: [h (k 0..1023) | x (k 1024..1250) | pad].
__global__ void k_setup(const float* __restrict__ Wih1, const float* __restrict__ Whh1,
                        const float* __restrict__ Wih2, const float* __restrict__ Whh2,
                        const float* __restrict__ Wih3, const float* __restrict__ Whh3,
                        const float* __restrict__ bih1, const float* __restrict__ bhh1,
                        const float* __restrict__ bih2, const float* __restrict__ bhh2,
                        const float* __restrict__ bih3, const float* __restrict__ bhh3) {
    const long TOT = (long)WTOT + 3L * NG;
    for (long idx = (long)blockIdx.x * blockDim.x + threadIdx.x; idx < TOT;
         idx += (long)gridDim.x * blockDim.x) {
        long r = idx;
        if (r < (long)WTOT) {
            int z, n, k;
            if (r < W1SZ)              { z = 0; n = (int)(r / KP1); k = (int)(r % KP1); }
            else if (r < W1SZ + W2SZ)  { long q = r - W1SZ; z = 1; n = (int)(q / KP2); k = (int)(q % KP2); }
            else                       { long q = r - W1SZ - W2SZ; z = 2; n = (int)(q / KP2); k = (int)(q % KP2); }
            int R = (n & 3) * HID_ + (n >> 2);   // ifgo-quad reorder
            float w = 0.0f;
            if (z == 0) {
                if (k < HID_)           w = Whh1[(size_t)R * HID_ + k];
                else if (k < HID_+INF)  w = Wih1[(size_t)R * INF + (k - HID_)];
            } else if (z == 1) {
                w = (k < HID_) ? Wih2[(size_t)R * HID_ + k] : Whh2[(size_t)R * HID_ + (k - HID_)];
            } else {
                w = (k < HID_) ? Wih3[(size_t)R * HID_ + k] : Whh3[(size_t)R * HID_ + (k - HID_)];
            }
            g_Wh[r] = __float2half_rn(w);
            continue;
        }
        r -= WTOT;
        {
            int L = (int)(r / NG), n = (int)(r % NG);
            int R = (n & 3) * HID_ + (n >> 2);
            float v = (L == 0) ? bih1[R] + bhh1[R]
                    : (L == 1) ? bih2[R] + bhh2[R]
                               : bih3[R] + bhh3[R];
            g_bias[r] = v;
        }
    }
}

// Wd fp16 hi/lo [n][k] padded to 256 rows
__global__ void k_setup_bd(const float* __restrict__ Wd) {
    int i = blockIdx.x * blockDim.x + threadIdx.x;
    if (i >= 256 * HID_) return;
    int n = i / HID_, k = i % HID_;
    float w = (n < INF) ? Wd[(size_t)n * HID_ + k] : 0.0f;
    __half hi = __float2half_rn(w);
    g_BdH[i] = hi;
    g_BdL[i] = __float2half_rn(w - __half2float(hi));
}

// ---------------- stage ALL x frames upfront (teacher frames + zero pads) ----
__global__ void stage_x(const float* __restrict__ rs) {
    long i = (long)blockIdx.x * blockDim.x + threadIdx.x;
    if (i >= (long)T_ * B_ * 256) return;
    int n = (int)(i & 255);
    int b = (int)((i >> 8) & 255);
    int t = (int)(i >> 16);
    float v = 0.0f;
    if (n < INF && (t % 10) < 5)
        v = rs[(size_t)b * (T_ * INF) + (size_t)t * INF + n];
    g_Ax[i] = __float2half_rn(v);
}

// ---------------- single persistent fused HMMA kernel: ALL 100 steps --------
// 148 persistent CTAs walk per-step ticket queues; cross-step dependencies
// (RAW + ping-pong WAR) enforced via g_cnt[(t,z,mtile)] done counters:
//   z0(t): cnt0(t-1,m)=32, cnt1(t-1,m)=32 [+ fbdone(t-1)=8 on free-run steps]
//   z1(t): cnt0,cnt1,cnt2(t-1,m)=32    z2(t): cnt1,cnt2(t-1,m)=32
//   fb(t): cnt2(t,m)=32
// Deadlock-free: step-t tickets pop only after step t-1's queue fully drained.
__global__ void __launch_bounds__(256, 1) gates_kernel(const float* __restrict__ bd) {
    extern __shared__ char dynsmem[];
    __shared__ int s_job;
    const int tid = threadIdx.x;
    const int warp = tid >> 5, lane = tid & 31;
    const int warpm = warp >> 2, warpn = warp & 3;
    const uint32_t sbase = smem_u32(dynsmem);

    int t = 0;
    for (;;) {
        if (tid == 0) s_job = (int)atomicAdd(&g_ticket[t], 1u);
        __syncthreads();
        const int jid = s_job;
        __syncthreads();   // protect s_job against next-iteration overwrite
        const int hasfb = (t < T_ - 1) && (((t + 1) % 10) >= 5);
        const int njobs = 384 + (hasfb ? 8 : 0);
        if (jid >= njobs) {
            if (++t >= T_) return;
            continue;
        }
        const int p = t & 1, pn = p ^ 1;
        const __half* __restrict__ Apar = g_A + (size_t)p * APAR;

        // ---- decode job ----
        int typ, z = 0, mbase, nbase, nch, asplit;
        const __half *ap0, *ap1 = nullptr, *bp;
        int as0, as1 = 0, bstr;
        if (jid < 256) {                       // z1 / z2
            typ = 0; z = 1 + (jid & 1);
            int idx = jid >> 1;
            mbase = (idx & 3) * 64; nbase = (idx >> 2) * 128;
            nch = 32; asplit = 32;
            ap0 = Apar + ((z == 2) ? (size_t)A2SZ : 0); as0 = KP2;
            bp  = g_Wh + ((z == 1) ? (size_t)W1SZ : (size_t)(W1SZ + W2SZ)); bstr = KP2;
        } else if (jid < 384) {                // z0: [h0 | x]
            typ = 0; z = 0;
            int idx = jid - 256;
            mbase = (idx & 3) * 64; nbase = (idx >> 2) * 128;
            nch = 20; asplit = 16;
            ap0 = Apar; as0 = KP2;
            ap1 = g_Ax + (size_t)t * (B_ * 256); as1 = 256;
            bp  = g_Wh; bstr = KP1;
        } else {                               // feedback: x(t+1) = h2(t)@Wd^T+bd
            typ = 1;
            int idx = jid - 384;
            mbase = (idx & 3) * 64; nbase = (idx >> 2) * 128;
            nch = 16; asplit = 16;
            ap0 = g_histH + (size_t)t * SL; as0 = HID_;
            bp  = g_BdH; bstr = HID_;
        }
        const int mt = mbase >> 6;

        // ---- dependency wait (tid 0 spins on L2-coherent counters) ----
        if (tid == 0) {
            if (typ == 1) {
                spin_ge(&g_cnt[t][2][mt], 32u);
            } else if (t > 0) {
                if (z == 0) {
                    spin_ge(&g_cnt[t-1][0][mt], 32u);
                    spin_ge(&g_cnt[t-1][1][mt], 32u);
                    if ((t % 10) >= 5) spin_ge(&g_fbdone[t-1], 8u);
                } else if (z == 1) {
                    spin_ge(&g_cnt[t-1][0][mt], 32u);
                    spin_ge(&g_cnt[t-1][1][mt], 32u);
                    spin_ge(&g_cnt[t-1][2][mt], 32u);
                } else {
                    spin_ge(&g_cnt[t-1][1][mt], 32u);
                    spin_ge(&g_cnt[t-1][2][mt], 32u);
                }
            }
        }
        __syncthreads();

        // ---- async stage loader: 1536 x 16B per stage, 6 per thread ----
        auto issue = [&](int ch) {
            if (ch < nch) {
                const uint32_t sb = sbase + (ch % NSTAGE) * GSTAGEB;
                const int k0 = ch << 6;
#pragma unroll
                for (int it = 0; it < 6; it++) {
                    int s = it * 256 + tid;           // 0..1535
                    if (s < 512) {                     // A tile: 64 rows x 8 c16
                        int r = s >> 3, c4 = s & 7;
                        const __half* gp = (ch < asplit)
                            ? ap0 + (size_t)(mbase + r) * as0 + k0 + c4 * 8
                            : ap1 + (size_t)(mbase + r) * as1 + (k0 - (asplit << 6)) + c4 * 8;
                        cp16(sb + r * PITCHG + c4 * 16, gp);
                    } else {                           // B tile: 128 rows x 8 c16
                        int sB = s - 512; int r = sB >> 3, c4 = sB & 7;
                        cp16(sb + TILEA + r * PITCHG + c4 * 16,
                             bp + (size_t)(nbase + r) * bstr + k0 + c4 * 8);
                    }
                }
            }
            cp_commit();
        };

        float acc[2][4][4];
#pragma unroll
        for (int mf = 0; mf < 2; mf++)
#pragma unroll
            for (int nf = 0; nf < 4; nf++)
#pragma unroll
                for (int i = 0; i < 4; i++) acc[mf][nf][i] = 0.0f;

        issue(0); issue(1);
        for (int ch = 0; ch < nch; ch++) {
            asm volatile("cp.async.wait_group 1;" ::: "memory");
            __syncthreads();
            issue(ch + 2);
            const uint32_t sb = sbase + (ch % NSTAGE) * GSTAGEB;
#pragma unroll
            for (int kk = 0; kk < 4; kk++) {
                uint32_t ah[2][4];
#pragma unroll
                for (int mf = 0; mf < 2; mf++) {
                    uint32_t addr = sb + (uint32_t)(warpm * 32 + mf * 16 + (lane & 15)) * PITCHG
                                  + kk * 32 + (lane >> 4) * 16;
                    ldm_x4(ah[mf], addr);
                }
                uint32_t bh[2][4];
#pragma unroll
                for (int nf2 = 0; nf2 < 2; nf2++) {
                    int nrow = warpn * 32 + nf2 * 16 + (lane & 7) + ((lane >> 4) << 3);
                    uint32_t addr = sb + TILEA + (uint32_t)nrow * PITCHG
                                  + kk * 32 + ((lane >> 3) & 1) * 16;
                    ldm_x4(bh[nf2], addr);
                }
#pragma unroll
                for (int mf = 0; mf < 2; mf++)
#pragma unroll
                    for (int nf = 0; nf < 4; nf++)
                        mma16816(acc[mf][nf], ah[mf],
                                 bh[nf >> 1][(nf & 1) * 2], bh[nf >> 1][(nf & 1) * 2 + 1]);
            }
        }

        if (typ == 0) {
            // ---- LSTM epilogue: shuffle c-frags into (i,f,g,o) quads ----
            const int c     = lane & 3;
            const int pairq = c >> 1;
            const int pos   = c & 1;
            const int rbase = lane >> 2;

            float* cpz = g_c + (size_t)z * SL;
            __half* dst0; __half* dst1 = nullptr;
            if (z == 0)      { dst0 = g_A + (size_t)pn * APAR; }
            else if (z == 1) { dst0 = g_A + (size_t)pn * APAR + 1024;
                               dst1 = g_A + (size_t)pn * APAR + A2SZ; }
            else             { dst0 = g_A + (size_t)pn * APAR + A2SZ + 1024; }

#pragma unroll
            for (int mf = 0; mf < 2; mf++) {
#pragma unroll
                for (int nf = 0; nf < 4; nf++) {
                    float a0 = acc[mf][nf][0], a1 = acc[mf][nf][1];
                    float a2 = acc[mf][nf][2], a3 = acc[mf][nf][3];
                    float p0 = __shfl_xor_sync(0xffffffffu, a0, 1);
                    float p1 = __shfl_xor_sync(0xffffffffu, a1, 1);
                    float p2 = __shfl_xor_sync(0xffffffffu, a2, 1);
                    float p3 = __shfl_xor_sync(0xffffffffu, a3, 1);
                    float iv, fv, gv, ov; int row;
                    if (pos == 0) { iv = a0; fv = a1; gv = p0; ov = p1; row = rbase; }
                    else          { iv = p2; fv = p3; gv = a2; ov = a3; row = rbase + 8; }
                    int n0 = nbase + warpn * 32 + nf * 8 + pairq * 4;
                    float4 bs = *(const float4*)(g_bias + z * NG + n0);
                    iv += bs.x; fv += bs.y; gv += bs.z; ov += bs.w;

                    int b = mbase + warpm * 32 + mf * 16 + row;
                    int j = n0 >> 2;
                    size_t co = (size_t)b * HID_ + j;
                    float cold = __ldcg(cpz + co);   // L2-coherent (persistent kernel)
                    float cn = sigf_(fv) * cold + sigf_(iv) * tanhf(gv);
                    float hn = sigf_(ov) * tanhf(cn);
                    __stcg(cpz + co, cn);
                    __half hh = __float2half_rn(hn);
                    dst0[(size_t)b * KP2 + j] = hh;
                    if (z == 1) dst1[(size_t)b * KP2 + j] = hh;
                    if (z == 2) {
                        size_t ho = ((size_t)t * B_ + b) * HID_ + j;
                        g_histH[ho] = hh;
                        g_histL[ho] = __float2half_rn(hn - __half2float(hh));
                    }
                }
            }
        } else {
            // ---- feedback epilogue: x(t+1) = acc + bd, fp16 into g_Ax ----
            const int rbase = lane >> 2;
            const int cbase = (lane & 3) * 2;
            __half* xd = g_Ax + (size_t)(t + 1) * (B_ * 256);
#pragma unroll
            for (int mf = 0; mf < 2; mf++) {
#pragma unroll
                for (int nf = 0; nf < 4; nf++) {
#pragma unroll
                    for (int i = 0; i < 4; i++) {
                        int row = mbase + warpm * 32 + mf * 16 + rbase + (i >> 1) * 8;
                        int n   = nbase + warpn * 32 + nf * 8 + cbase + (i & 1);
                        if (n < INF)
                            xd[(size_t)row * 256 + n] =
                                __float2half_rn(acc[mf][nf][i] + bd[n]);
                    }
                }
            }
        }

        // ---- publish completion ----
        __threadfence();
        asm volatile("cp.async.wait_group 0;" ::: "memory");
        __syncthreads();
        if (tid == 0) {
            if (typ == 0) atomicAdd(&g_cnt[t][z][mt], 1u);
            else          atomicAdd(&g_fbdone[t], 1u);
        }
    }
}

// ---------------- final dense via HMMA (3-term fp16, split hist + split Wd) ----
__global__ void __launch_bounds__(256, 1) dense_kernel(float* __restrict__ out,
                                                       const float* __restrict__ bd) {
    extern __shared__ char dynsmem[];
    const int tid = threadIdx.x;
    const int warp = tid >> 5, lane = tid & 31;
    const int warpm = warp >> 2, warpn = warp & 3;
    const int mbase = (blockIdx.x >> 1) * 128;
    const int nbase = (blockIdx.x & 1) * 128;
    const int nch = HID_ >> 5;  // 32
    const uint32_t sbase = smem_u32(dynsmem);

    auto issue = [&](int ch) {
        if (ch < nch) {
            const uint32_t sb = sbase + (ch % NSTAGE) * DSTAGEB;
            const int k0 = ch << 5;
#pragma unroll
            for (int it = 0; it < 8; it++) {
                int s = it * 256 + tid;
                int tile = s >> 9;
                int r  = (s & 511) >> 2;
                int c4 = s & 3;
                uint32_t d = sb + tile * TILE2 + r * PITCH2 + c4 * 16;
                const __half* gp;
                if (tile == 0)      gp = g_histH + (size_t)(mbase + r) * HID_ + k0 + c4 * 8;
                else if (tile == 1) gp = g_histL + (size_t)(mbase + r) * HID_ + k0 + c4 * 8;
                else if (tile == 2) gp = g_BdH   + (size_t)(nbase + r) * HID_ + k0 + c4 * 8;
                else                gp = g_BdL   + (size_t)(nbase + r) * HID_ + k0 + c4 * 8;
                cp16(d, gp);
            }
        }
        cp_commit();
    };

    float acc[4][4][4];
#pragma unroll
    for (int mf = 0; mf < 4; mf++)
#pragma unroll
        for (int nf = 0; nf < 4; nf++)
#pragma unroll
            for (int i = 0; i < 4; i++) acc[mf][nf][i] = 0.0f;

    issue(0); issue(1);
    for (int ch = 0; ch < nch; ch++) {
        asm volatile("cp.async.wait_group 1;" ::: "memory");
        __syncthreads();
        issue(ch + 2);
        const uint32_t sb = sbase + (ch % NSTAGE) * DSTAGEB;
#pragma unroll
        for (int kk = 0; kk < 2; kk++) {
            uint32_t ah[4][4], al[4][4];
#pragma unroll
            for (int mf = 0; mf < 4; mf++) {
                uint32_t addr = sb + (uint32_t)(warpm * 64 + mf * 16 + (lane & 15)) * PITCH2
                              + kk * 32 + (lane >> 4) * 16;
                ldm_x4(ah[mf], addr);
                ldm_x4(al[mf], addr + TILE2);
            }
            uint32_t bh[2][4], bl[2][4];
#pragma unroll
            for (int nf2 = 0; nf2 < 2; nf2++) {
                int nrow = warpn * 32 + nf2 * 16 + (lane & 7) + ((lane >> 4) << 3);
                uint32_t addr = sb + 2 * TILE2 + (uint32_t)nrow * PITCH2
                              + kk * 32 + ((lane >> 3) & 1) * 16;
                ldm_x4(bh[nf2], addr);
                ldm_x4(bl[nf2], addr + TILE2);
            }
#pragma unroll
            for (int mf = 0; mf < 4; mf++)
#pragma unroll
                for (int nf = 0; nf < 4; nf++) {
                    const int nf2 = nf >> 1, h = nf & 1;
                    uint32_t b0h = bh[nf2][h * 2], b1h = bh[nf2][h * 2 + 1];
                    uint32_t b0l = bl[nf2][h * 2], b1l = bl[nf2][h * 2 + 1];
                    mma16816(acc[mf][nf], ah[mf], b0h, b1h);
                    mma16816(acc[mf][nf], ah[mf], b0l, b1l);
                    mma16816(acc[mf][nf], al[mf], b0h, b1h);
                }
        }
    }

    const int rbase = lane >> 2;
    const int cbase = (lane & 3) * 2;
#pragma unroll
    for (int mf = 0; mf < 4; mf++) {
#pragma unroll
        for (int nf = 0; nf < 4; nf++) {
#pragma unroll
            for (int i = 0; i < 4; i++) {
                int row = mbase + warpm * 64 + mf * 16 + rbase + (i >> 1) * 8;
                int n   = nbase + warpn * 32 + nf * 8 + cbase + (i & 1);
                if (n < INF) {
                    int tt = row >> 8, bb = row & 255;
                    out[(size_t)bb * (T_ * INF) + (size_t)tt * INF + n] =
                        acc[mf][nf][i] + bd[n];
                }
            }
        }
    }
}

// ---------------- launch ----------------
extern "C" void kernel_launch(void* const* d_in, const int* in_sizes, int n_in,
                              void* d_out, int out_size) {
    (void)in_sizes; (void)n_in; (void)out_size;
    const float* rs   = (const float*)d_in[0];
    const float* Wih1 = (const float*)d_in[1];
    const float* Whh1 = (const float*)d_in[2];
    const float* bih1 = (const float*)d_in[3];
    const float* bhh1 = (const float*)d_in[4];
    const float* Wih2 = (const float*)d_in[5];
    const float* Whh2 = (const float*)d_in[6];
    const float* bih2 = (const float*)d_in[7];
    const float* bhh2 = (const float*)d_in[8];
    const float* Wih3 = (const float*)d_in[9];
    const float* Whh3 = (const float*)d_in[10];
    const float* bih3 = (const float*)d_in[11];
    const float* bhh3 = (const float*)d_in[12];
    const float* Wd   = (const float*)d_in[13];
    const float* bd   = (const float*)d_in[14];
    float* out = (float*)d_out;

    cudaFuncSetAttribute(gates_kernel, cudaFuncAttributeMaxDynamicSharedMemorySize, GSMEM);
    cudaFuncSetAttribute(dense_kernel, cudaFuncAttributeMaxDynamicSharedMemorySize, DSMEM_D);

    k_zero<<<2048, 256>>>();
    k_setup<<<4096, 256>>>(Wih1, Whh1, Wih2, Whh2, Wih3, Whh3,
                           bih1, bhh1, bih2, bhh2, bih3, bhh3);
    k_setup_bd<<<(256 * HID_ + 255) / 256, 256>>>(Wd);
    stage_x<<<(T_ * B_ * 256) / 256, 256>>>(rs);

    gates_kernel<<<NCTA, 256, GSMEM>>>(bd);      // ALL 100 steps, one launch
    dense_kernel<<<400, 256, DSMEM_D>>>(out, bd);
}